// round 13
// baseline (speedup 1.0000x reference)
#include <cuda_runtime.h>
#include <cuda_fp16.h>

#define Bn   64
#define Cn   122
#define Tn   500
#define COn  64
#define Dn   128
#define Hn   8
#define FFn  256
#define Lln  2
#define BC   (Bn*Cn)
#define EPSf 1e-5f

typedef unsigned long long ull;
typedef unsigned int uint32;

/* ---------------- scratch (device globals; no allocation) ---------------- */
__device__ float g_tok[BC*Dn];
__device__ float g_qkv[BC*3*Dn];
__device__ float g_ctx[BC*Dn];
__device__ float g_ff [BC*FFn];

/* Winograd F(4,5) matrices, points {0,1,-1,2,-2,1/2,-1/2,inf}.
   Verified: sum_j AT[i][j]*G[j][k]*BT[j][l] = delta_{l,i+k}. */
__device__ const float c_BT[8][8] = {
 {-1.f, 0.f, 5.25f, 0.f, -5.25f, 0.f, 1.f, 0.f},
 {0.f, 1.f, 1.f, -4.25f, -4.25f, 1.f, 1.f, 0.f},
 {0.f, -1.f, 1.f, 4.25f, -4.25f, -1.f, 1.f, 0.f},
 {0.f, 0.5f, 0.25f, -2.5f, -1.25f, 2.f, 1.f, 0.f},
 {0.f, -0.5f, 0.25f, 2.5f, -1.25f, -2.f, 1.f, 0.f},
 {0.f, 2.f, 4.f, -2.5f, -5.f, 0.5f, 1.f, 0.f},
 {0.f, -2.f, 4.f, 2.5f, -5.f, -0.5f, 1.f, 0.f},
 {0.f, -1.f, 0.f, 5.25f, 0.f, -5.25f, 0.f, 1.f}};
/* G scaled by 32 (epilogue divides by 32 via sA2) */
__device__ const float c_G32[8][5] = {
 {-32.f, 0.f, 0.f, 0.f, 0.f},
 {-7.1111111f, -7.1111111f, -7.1111111f, -7.1111111f, -7.1111111f},
 {-7.1111111f, 7.1111111f, -7.1111111f, 7.1111111f, -7.1111111f},
 {0.35555556f, 0.71111111f, 1.42222222f, 2.84444444f, 5.68888889f},
 {0.35555556f, -0.71111111f, 1.42222222f, -2.84444444f, 5.68888889f},
 {22.7555556f, 11.3777778f, 5.68888889f, 2.84444444f, 1.42222222f},
 {22.7555556f, -11.3777778f, 5.68888889f, -2.84444444f, 1.42222222f},
 {0.f, 0.f, 0.f, 0.f, 32.f}};
__device__ const float c_AT[4][8] = {
 {1.f, 1.f, 1.f, 1.f, 1.f, 1.f, 1.f, 0.f},
 {0.f, 1.f, -1.f, 2.f, -2.f, 0.5f, -0.5f, 0.f},
 {0.f, 1.f, 1.f, 4.f, 4.f, 0.25f, 0.25f, 0.f},
 {0.f, 1.f, -1.f, 8.f, -8.f, 0.125f, -0.125f, 1.f}};

/* fast erf-GELU: Abramowitz-Stegun 7.1.26, |erf err| <= 1.5e-7 */
__device__ __forceinline__ float gelu_f(float x){
    float z  = fabsf(x) * 0.70710678118654752440f;
    float t  = __fdividef(1.0f, 1.0f + 0.3275911f*z);
    float poly = t*(0.254829592f + t*(-0.284496736f +
                 t*(1.421413741f + t*(-1.453152027f + t*1.061405429f))));
    float erfz = 1.0f - poly*__expf(-z*z);
    float s = copysignf(erfz, x);
    return 0.5f*x*(1.0f + s);
}

/* packed f32x2 helpers (transformer GEMMs) */
__device__ __forceinline__ ull pk(float a, float b){
    ull r; asm("mov.b64 %0, {%1, %2};" : "=l"(r) : "f"(a), "f"(b)); return r;
}
__device__ __forceinline__ void fma2(ull& d, ull a, ull b){
    asm("fma.rn.f32x2 %0, %1, %2, %0;" : "+l"(d) : "l"(a), "l"(b));
}
__device__ __forceinline__ float2 upk(ull a){
    float2 f; asm("mov.b64 {%0, %1}, %2;" : "=f"(f.x), "=f"(f.y) : "l"(a)); return f;
}

/* fp16 mma m16n8k16, fp32 accum */
__device__ __forceinline__ void mma_f16(float* c,
    uint32 a0, uint32 a1, uint32 a2, uint32 a3, uint32 b0, uint32 b1){
    asm volatile("mma.sync.aligned.m16n8k16.row.col.f32.f16.f16.f32 "
        "{%0,%1,%2,%3}, {%4,%5,%6,%7}, {%8,%9}, {%0,%1,%2,%3};"
        : "+f"(c[0]), "+f"(c[1]), "+f"(c[2]), "+f"(c[3])
        : "r"(a0), "r"(a1), "r"(a2), "r"(a3), "r"(b0), "r"(b1));
}

__device__ __forceinline__ uint32 h2pack(__half lo, __half hi){
    __half2 h = __halves2half2(lo, hi);
    return *(uint32*)&h;
}

/* SMEM layout (bytes) */
#define SH1_OFF   0        /* float[64*264] 67584 */
#define W2F_OFF   67584    /* float[64*320] 81920 (raw conv2 weights) */
#define VH_OFF    149504   /* uint32[32*72] 9216 */
#define VL_OFF    158720
#define UH_OFF    167936   /* uint32[64*36] 9216 */
#define UL_OFF    177152
#define SX_OFF    186368   /* float[512] */
#define SW1_OFF   188416   /* float[576] */
#define SAB_OFF   190720   /* 4 x float[64] */
#define SPART_OFF 191744   /* float[64] */
#define SH2_OFF   192000   /* float[64] */
#define CONV_SMEM 192256

/* ============================================================
   Kernel 1: per-(b,c) fused conv pipeline, 512 threads, Winograd F(4,5).
   conv2: y[co][4*tile+i] = sum_p AT[i][p] * M_p[co][tile],
     M_p = U_p[64co x 64ci] @ V_p[64ci x 64tile]   (3-term fp16 split)
   U_p = 32*G_p*w (per point from SMEM fp32 weights),
   V_p[ci][tile] = sum_j BT[p][j]*h1[ci][4*tile + j - 2].
   ============================================================ */
__global__ void __launch_bounds__(512, 1) conv_kernel(
    const float* __restrict__ x,
    const float* __restrict__ w1, const float* __restrict__ cb1,
    const float* __restrict__ g1, const float* __restrict__ be1,
    const float* __restrict__ m1, const float* __restrict__ v1,
    const float* __restrict__ w2, const float* __restrict__ cb2,
    const float* __restrict__ g2, const float* __restrict__ be2,
    const float* __restrict__ m2, const float* __restrict__ v2,
    const float* __restrict__ pw, const float* __restrict__ pb,
    const float* __restrict__ emb, float* __restrict__ tok)
{
    extern __shared__ char smraw[];
    float*  sh1f  = (float*)(smraw + SH1_OFF);    /* [64][264], data at col+2 */
    float*  w2f   = (float*)(smraw + W2F_OFF);    /* [64][320] */
    uint32* VH    = (uint32*)(smraw + VH_OFF);    /* [32 cipair][72] */
    uint32* VL    = (uint32*)(smraw + VL_OFF);
    uint32* UH    = (uint32*)(smraw + UH_OFF);    /* [64 co][36] */
    uint32* UL    = (uint32*)(smraw + UL_OFF);
    float*  sx    = (float*)(smraw + SX_OFF);
    float*  sw1   = (float*)(smraw + SW1_OFF);
    float*  sA1   = (float*)(smraw + SAB_OFF);
    float*  sB1   = sA1 + 64;
    float*  sA2   = sA1 + 128;
    float*  sB2   = sA1 + 192;
    float*  spart = (float*)(smraw + SPART_OFF);
    float*  sh2   = (float*)(smraw + SH2_OFF);

    const int bc  = blockIdx.x;
    const int tid = threadIdx.x;
    const int wid = tid >> 5, lane = tid & 31;
    const int g   = lane >> 2, t4 = lane & 3;
    const int mc  = wid & 3,  tc  = wid >> 2;    /* 4x4 warp grid */

    /* ---- phase 0: loads ---- */
    {
        int t = tid - 4;
        sx[tid] = (t >= 0 && t < Tn) ? x[bc*Tn + t] : 0.f;
    }
    for (int i = tid; i < COn*9; i += 512) sw1[i] = w1[i];
    for (int i = tid; i < COn*320; i += 512) w2f[i] = w2[i];
    if (tid < 64) {
        float a1 = g1[tid]*rsqrtf(v1[tid]+EPSf);
        sA1[tid] = a1;  sB1[tid] = (cb1[tid]-m1[tid])*a1 + be1[tid];
        float a2 = g2[tid]*rsqrtf(v2[tid]+EPSf);
        sA2[tid] = a2;  sB2[tid] = (cb2[tid]-m2[tid])*a2 + be2[tid];
        spart[tid] = 0.f;
    }
    /* zero sh1 pad cols {0,1} U [252,264) */
    for (int i = tid; i < 64*14; i += 512) {
        int row = i / 14, j = i - row*14;
        int col = (j < 2) ? j : (250 + j);
        sh1f[row*264 + col] = 0.f;
    }
    __syncthreads();

    /* ---- conv1 + BN + GELU + maxpool(2) -> sh1f fp32 ---- */
    for (int i = tid; i < COn*250; i += 512) {
        int co = i / 250; int tp = i - co*250;
        const float* wp = &sw1[co*9];
        const float* xp = &sx[2*tp];
        float a0 = 0.f, a1 = 0.f;
        #pragma unroll
        for (int k = 0; k < 9; k++) { a0 += xp[k]*wp[k]; a1 += xp[k+1]*wp[k]; }
        float A = sA1[co], Bv = sB1[co];
        float y0 = gelu_f(a0*A + Bv);
        float y1 = gelu_f(a1*A + Bv);
        sh1f[co*264 + 2 + tp] = fmaxf(y0, y1);
    }

    /* ---- Winograd point loop ---- */
    float y_acc[2][4][4];
    #pragma unroll
    for (int nj = 0; nj < 2; nj++)
        #pragma unroll
        for (int r = 0; r < 4; r++)
            #pragma unroll
            for (int i = 0; i < 4; i++) y_acc[nj][r][i] = 0.f;

    for (int p = 0; p < 8; p++) {
        __syncthreads();
        float bt[8], gg[5], at[4];
        #pragma unroll
        for (int j = 0; j < 8; j++) bt[j] = c_BT[p][j];
        #pragma unroll
        for (int k = 0; k < 5; k++) gg[k] = c_G32[p][k];
        #pragma unroll
        for (int i = 0; i < 4; i++) at[i] = c_AT[i][p];

        /* build V_p: [cipair][tile], hi/lo fp16 */
        for (int idx = tid; idx < 32*64; idx += 512) {
            int cp = idx >> 6, tile = idx & 63;
            const float* r0 = &sh1f[(2*cp)*264 + 4*tile];
            const float* r1 = r0 + 264;
            float4 q0 = *(const float4*)r0;
            float4 q1 = *(const float4*)(r0 + 4);
            float4 s0 = *(const float4*)r1;
            float4 s1 = *(const float4*)(r1 + 4);
            float v0 = bt[0]*q0.x + bt[1]*q0.y + bt[2]*q0.z + bt[3]*q0.w
                     + bt[4]*q1.x + bt[5]*q1.y + bt[6]*q1.z + bt[7]*q1.w;
            float v1 = bt[0]*s0.x + bt[1]*s0.y + bt[2]*s0.z + bt[3]*s0.w
                     + bt[4]*s1.x + bt[5]*s1.y + bt[6]*s1.z + bt[7]*s1.w;
            __half h0 = __float2half_rn(v0);
            __half h1v = __float2half_rn(v1);
            __half l0 = __float2half_rn(v0 - __half2float(h0));
            __half l1 = __float2half_rn(v1 - __half2float(h1v));
            VH[cp*72 + tile] = h2pack(h0, h1v);
            VL[cp*72 + tile] = h2pack(l0, l1);
        }
        /* build U_p: [co][q] (q = ci-pair), hi/lo fp16, scaled x32 */
        for (int idx = tid; idx < 64*32; idx += 512) {
            int co = idx >> 5, q = idx & 31;
            const float* wp0 = &w2f[co*320 + (2*q)*5];
            float u0 = 0.f, u1 = 0.f;
            #pragma unroll
            for (int k = 0; k < 5; k++) {
                u0 += gg[k]*wp0[k];
                u1 += gg[k]*wp0[5 + k];
            }
            __half h0 = __float2half_rn(u0);
            __half h1v = __float2half_rn(u1);
            __half l0 = __float2half_rn(u0 - __half2float(h0));
            __half l1 = __float2half_rn(u1 - __half2float(h1v));
            UH[co*36 + q] = h2pack(h0, h1v);
            UL[co*36 + q] = h2pack(l0, l1);
        }
        __syncthreads();

        /* GEMM_p: warp tile 16co x 16tiles; K=64 (4 k-steps); 3-term split */
        float acc[2][4];
        #pragma unroll
        for (int nj = 0; nj < 2; nj++)
            #pragma unroll
            for (int r = 0; r < 4; r++) acc[nj][r] = 0.f;

        #pragma unroll
        for (int s = 0; s < 4; s++) {
            int q0 = s*8 + t4;
            int ra  = (mc*16 + g)*36 + q0;
            int rb2 = ra + 8*36;
            uint32 aH0 = UH[ra],   aH1 = UH[rb2];
            uint32 aH2 = UH[ra+4], aH3 = UH[rb2+4];
            uint32 aL0 = UL[ra],   aL1 = UL[rb2];
            uint32 aL2 = UL[ra+4], aL3 = UL[rb2+4];
            #pragma unroll
            for (int nj = 0; nj < 2; nj++) {
                int n  = tc*16 + nj*8 + g;
                int rv = (s*8 + t4)*72 + n;
                uint32 bh0 = VH[rv], bh1 = VH[rv + 4*72];
                uint32 bl0 = VL[rv], bl1 = VL[rv + 4*72];
                mma_f16(acc[nj], aH0, aH1, aH2, aH3, bh0, bh1);
                mma_f16(acc[nj], aL0, aL1, aL2, aL3, bh0, bh1);
                mma_f16(acc[nj], aH0, aH1, aH2, aH3, bl0, bl1);
            }
        }

        /* y_acc += AT[:,p] * M_p */
        #pragma unroll
        for (int nj = 0; nj < 2; nj++)
            #pragma unroll
            for (int r = 0; r < 4; r++) {
                float m = acc[nj][r];
                #pragma unroll
                for (int i = 0; i < 4; i++) y_acc[nj][r][i] += at[i]*m;
            }
    }

    /* ---- epilogue: BN + GELU + mean partials ---- */
    {
        const int co0 = mc*16 + g, co1 = co0 + 8;
        const float A0 = sA2[co0]*(1.0f/32.0f), B0 = sB2[co0];
        const float A1 = sA2[co1]*(1.0f/32.0f), B1 = sB2[co1];
        float s0 = 0.f, s1 = 0.f;
        #pragma unroll
        for (int nj = 0; nj < 2; nj++) {
            #pragma unroll
            for (int r = 0; r < 4; r++) {
                int tile = tc*16 + nj*8 + 2*t4 + (r & 1);
                float A = (r < 2) ? A0 : A1;
                float Bv = (r < 2) ? B0 : B1;
                #pragma unroll
                for (int i = 0; i < 4; i++) {
                    int t = 4*tile + i;
                    if (t < 250) {
                        float v = gelu_f(y_acc[nj][r][i]*A + Bv);
                        if (r < 2) s0 += v; else s1 += v;
                    }
                }
            }
        }
        s0 += __shfl_xor_sync(0xffffffffu, s0, 1);
        s0 += __shfl_xor_sync(0xffffffffu, s0, 2);
        s1 += __shfl_xor_sync(0xffffffffu, s1, 1);
        s1 += __shfl_xor_sync(0xffffffffu, s1, 2);
        if (t4 == 0) {
            atomicAdd(&spart[co0], s0);
            atomicAdd(&spart[co1], s1);
        }
    }
    __syncthreads();
    if (tid < 64) sh2[tid] = spart[tid] * (1.f/250.f);
    __syncthreads();

    /* proj + elec_emb -> tok */
    if (tid < 128) {
        const int d = tid;
        float acc2 = pb[d];
        const float* pwr = &pw[d*COn];
        #pragma unroll 8
        for (int c = 0; c < 64; c++) acc2 += sh2[c]*__ldg(&pwr[c]);
        int cidx = bc % Cn;
        tok[bc*Dn + d] = acc2 + emb[cidx*Dn + d];
    }
}

/* ============================================================
   Kernel 2: tiled GEMM  Y[M,N] = act(X[M,K] @ W[N,K]^T + bias)
   ============================================================ */
__global__ __launch_bounds__(256) void gemm_kernel(
    const float* __restrict__ X, const float* __restrict__ W,
    const float* __restrict__ bias, float* __restrict__ Y,
    int K, int N, int actGelu)
{
    extern __shared__ float sm[];
    float* sxT = sm;            /* [K][40] */
    float* swt = sm + K*40;     /* [K][65] */
    const int row0 = blockIdx.x*32;
    const int e0   = blockIdx.y*64;
    const int tid  = threadIdx.x;

    for (int li = tid; li < 32*K; li += 256) {
        int r = li / K, d = li - r*K;
        sxT[d*40 + r] = X[(row0+r)*K + d];
    }
    for (int li = tid; li < 64*K; li += 256) {
        int e = li / K, d = li - e*K;
        swt[d*65 + e] = W[(e0+e)*K + d];
    }
    __syncthreads();

    const int e_local = tid & 63, tg = tid >> 6;
    float bb = bias[e0 + e_local];
    ull acc[4];
    #pragma unroll
    for (int j = 0; j < 4; j++) acc[j] = pk(bb, bb);
    #pragma unroll 4
    for (int d = 0; d < K; d++) {
        ull Wp = pk(swt[d*65 + e_local], swt[d*65 + e_local]);
        const ull* tp = (const ull*)&sxT[d*40 + tg*8];
        fma2(acc[0], Wp, tp[0]);
        fma2(acc[1], Wp, tp[1]);
        fma2(acc[2], Wp, tp[2]);
        fma2(acc[3], Wp, tp[3]);
    }
    #pragma unroll
    for (int j = 0; j < 4; j++) {
        float2 y = upk(acc[j]);
        if (actGelu) { y.x = gelu_f(y.x); y.y = gelu_f(y.y); }
        Y[(row0 + tg*8 + 2*j  )*N + e0 + e_local] = y.x;
        Y[(row0 + tg*8 + 2*j+1)*N + e0 + e_local] = y.y;
    }
}

/* ============================================================
   Kernel 3: GEMM (N=128) + residual + LayerNorm epilogue
   ============================================================ */
__global__ __launch_bounds__(256) void gemm_ln_kernel(
    const float* __restrict__ X, const float* __restrict__ W,
    const float* __restrict__ bias,
    const float* __restrict__ Res,
    const float* __restrict__ lng, const float* __restrict__ lnb,
    float* __restrict__ Out, int K)
{
    extern __shared__ float sm[];
    float* sxT = sm;               /* [K][40]  */
    float* swt = sm + K*40;        /* [K][65]  */
    float* sy  = swt + K*65;       /* [32][132] */
    const int row0 = blockIdx.x*32;
    const int tid  = threadIdx.x;

    for (int li = tid; li < 32*K; li += 256) {
        int r = li / K, d = li - r*K;
        sxT[d*40 + r] = X[(row0+r)*K + d];
    }
    const int e_local = tid & 63, tg = tid >> 6;

    for (int e0 = 0; e0 < 128; e0 += 64) {
        __syncthreads();
        for (int li = tid; li < 64*K; li += 256) {
            int e = li / K, d = li - e*K;
            swt[d*65 + e] = W[(e0+e)*K + d];
        }
        __syncthreads();
        float bb = bias[e0 + e_local];
        ull acc[4];
        #pragma unroll
        for (int j = 0; j < 4; j++) acc[j] = pk(bb, bb);
        #pragma unroll 4
        for (int d = 0; d < K; d++) {
            ull Wp = pk(swt[d*65 + e_local], swt[d*65 + e_local]);
            const ull* tp = (const ull*)&sxT[d*40 + tg*8];
            fma2(acc[0], Wp, tp[0]);
            fma2(acc[1], Wp, tp[1]);
            fma2(acc[2], Wp, tp[2]);
            fma2(acc[3], Wp, tp[3]);
        }
        #pragma unroll
        for (int j = 0; j < 4; j++) {
            float2 y = upk(acc[j]);
            sy[(tg*8 + 2*j  )*132 + e0 + e_local] = y.x;
            sy[(tg*8 + 2*j+1)*132 + e0 + e_local] = y.y;
        }
    }
    __syncthreads();

    const int w = tid >> 5, lane = tid & 31;
    for (int q = 0; q < 4; q++) {
        int r = w*4 + q;
        float z[4]; float s1 = 0.f, s2 = 0.f;
        #pragma unroll
        for (int i = 0; i < 4; i++) {
            int idx = lane + 32*i;
            float zz = sy[r*132 + idx] + Res[(row0+r)*128 + idx];
            z[i] = zz; s1 += zz; s2 += zz*zz;
        }
        #pragma unroll
        for (int o = 16; o > 0; o >>= 1) {
            s1 += __shfl_xor_sync(0xffffffffu, s1, o);
            s2 += __shfl_xor_sync(0xffffffffu, s2, o);
        }
        float mean = s1*(1.f/128.f);
        float var  = s2*(1.f/128.f) - mean*mean;
        float rs   = rsqrtf(var + EPSf);
        #pragma unroll
        for (int i = 0; i < 4; i++) {
            int idx = lane + 32*i;
            Out[(row0+r)*128 + idx] = (z[i]-mean)*rs*lng[idx] + lnb[idx];
        }
    }
}

/* ============================================================
   Kernel 4: attention per (b, head). seq=122, dh=16.
   ============================================================ */
__global__ __launch_bounds__(128) void attn_kernel(
    const float* __restrict__ qkv, float* __restrict__ ctx)
{
    const int b = blockIdx.x >> 3, h = blockIdx.x & 7;
    extern __shared__ float sm[];
    float* sq = sm;                 /* [122][17] */
    float* sk = sm + 122*17;
    float* sv = sm + 2*122*17;
    float* sattb = sm + 3*122*17;   /* [4][128] */
    const int tid = threadIdx.x;

    for (int li = tid; li < 122*16; li += 128) {
        int s = li >> 4, d = li & 15;
        int base = (b*Cn + s)*384 + h*16 + d;
        sq[s*17 + d] = qkv[base];
        sk[s*17 + d] = qkv[base + 128];
        sv[s*17 + d] = qkv[base + 256];
    }
    __syncthreads();

    const int w = tid >> 5, lane = tid & 31;
    float* satt = sattb + w*128;

    for (int i = w; i < Cn; i += 4) {
        float sc[4];
        #pragma unroll
        for (int c = 0; c < 4; c++) {
            int kk = lane + 32*c;
            if (kk < Cn) {
                float s = 0.f;
                #pragma unroll
                for (int d = 0; d < 16; d++) s += sq[i*17 + d]*sk[kk*17 + d];
                sc[c] = s*0.25f;
            } else sc[c] = -1e30f;
        }
        float mx = fmaxf(fmaxf(sc[0], sc[1]), fmaxf(sc[2], sc[3]));
        #pragma unroll
        for (int o = 16; o > 0; o >>= 1) mx = fmaxf(mx, __shfl_xor_sync(0xffffffffu, mx, o));
        float p[4]; float sum = 0.f;
        #pragma unroll
        for (int c = 0; c < 4; c++) {
            int kk = lane + 32*c;
            p[c] = (kk < Cn) ? __expf(sc[c]-mx) : 0.f;
            sum += p[c];
        }
        #pragma unroll
        for (int o = 16; o > 0; o >>= 1) sum += __shfl_xor_sync(0xffffffffu, sum, o);
        float inv = __fdividef(1.f, sum);
        #pragma unroll
        for (int c = 0; c < 4; c++) {
            int kk = lane + 32*c;
            if (kk < Cn) satt[kk] = p[c]*inv;
        }
        __syncwarp();
        int d = lane & 15, half = lane >> 4;
        float a = 0.f;
        int j0 = half*61;
        for (int j = j0; j < j0 + 61; j++) a += satt[j]*sv[j*17 + d];
        a += __shfl_xor_sync(0xffffffffu, a, 16);
        if (lane < 16) ctx[(b*Cn + i)*Dn + h*16 + d] = a;
        __syncwarp();
    }
}

/* ============================================================
   Kernel 5: mean over C + per-subject head -> out[64,4]
   ============================================================ */
__global__ __launch_bounds__(128) void head_kernel(
    const float* __restrict__ tok, const int* __restrict__ sid,
    const float* __restrict__ hw, const float* __restrict__ hb,
    float* __restrict__ out)
{
    const int b = blockIdx.x;
    __shared__ float sp[128];
    const int d = threadIdx.x;
    float s = 0.f;
    for (int c = 0; c < Cn; c++) s += tok[(b*Cn + c)*Dn + d];
    sp[d] = s*(1.f/(float)Cn);
    __syncthreads();
    const int cls = threadIdx.x >> 5, lane = threadIdx.x & 31;
    const int sb = sid[b];
    float a = 0.f;
    #pragma unroll
    for (int i = 0; i < 4; i++) {
        int dd = lane + 32*i;
        a += sp[dd]*hw[(sb*4 + cls)*Dn + dd];
    }
    #pragma unroll
    for (int o = 16; o > 0; o >>= 1) a += __shfl_xor_sync(0xffffffffu, a, o);
    if (lane == 0) out[b*4 + cls] = a + hb[sb*4 + cls];
}

/* ============================================================ */
extern "C" void kernel_launch(void* const* d_in, const int* in_sizes, int n_in,
                              void* d_out, int out_size)
{
    const float* x       = (const float*)d_in[0];
    const int*   sid     = (const int*  )d_in[1];
    const float* conv1_w = (const float*)d_in[2];
    const float* conv1_b = (const float*)d_in[3];
    const float* bn1_g   = (const float*)d_in[4];
    const float* bn1_b   = (const float*)d_in[5];
    const float* bn1_m   = (const float*)d_in[6];
    const float* bn1_v   = (const float*)d_in[7];
    const float* conv2_w = (const float*)d_in[8];
    const float* conv2_b = (const float*)d_in[9];
    const float* bn2_g   = (const float*)d_in[10];
    const float* bn2_b   = (const float*)d_in[11];
    const float* bn2_m   = (const float*)d_in[12];
    const float* bn2_v   = (const float*)d_in[13];
    const float* proj_w  = (const float*)d_in[14];
    const float* proj_b  = (const float*)d_in[15];
    const float* emb     = (const float*)d_in[16];
    const float* qkv_w   = (const float*)d_in[17];
    const float* qkv_b   = (const float*)d_in[18];
    const float* out_w   = (const float*)d_in[19];
    const float* out_b   = (const float*)d_in[20];
    const float* ln1_g   = (const float*)d_in[21];
    const float* ln1_b   = (const float*)d_in[22];
    const float* ff1_w   = (const float*)d_in[23];
    const float* ff1_b   = (const float*)d_in[24];
    const float* ff2_w   = (const float*)d_in[25];
    const float* ff2_b   = (const float*)d_in[26];
    const float* ln2_g   = (const float*)d_in[27];
    const float* ln2_b   = (const float*)d_in[28];
    const float* heads_w = (const float*)d_in[29];
    const float* heads_b = (const float*)d_in[30];

    const int GEMM_SMEM   = (128*40 + 128*65)*4;           /* 53760 B  */
    const int GLN_SMEM128 = (128*40 + 128*65 + 32*132)*4;  /* 70656 B  */
    const int GLN_SMEM256 = (256*40 + 256*65 + 32*132)*4;  /* 124416 B */
    const int ATTN_SMEM   = (3*122*17 + 4*128)*4;          /* 26936 B  */

    cudaFuncSetAttribute(conv_kernel,    cudaFuncAttributeMaxDynamicSharedMemorySize, CONV_SMEM);
    cudaFuncSetAttribute(gemm_kernel,    cudaFuncAttributeMaxDynamicSharedMemorySize, GEMM_SMEM);
    cudaFuncSetAttribute(gemm_ln_kernel, cudaFuncAttributeMaxDynamicSharedMemorySize, GLN_SMEM256);

    float* tokp = nullptr; float* qkvp = nullptr; float* ctxp = nullptr; float* ffp = nullptr;
    cudaGetSymbolAddress((void**)&tokp, g_tok);
    cudaGetSymbolAddress((void**)&qkvp, g_qkv);
    cudaGetSymbolAddress((void**)&ctxp, g_ctx);
    cudaGetSymbolAddress((void**)&ffp,  g_ff);

    conv_kernel<<<BC, 512, CONV_SMEM>>>(
        x, conv1_w, conv1_b, bn1_g, bn1_b, bn1_m, bn1_v,
        conv2_w, conv2_b, bn2_g, bn2_b, bn2_m, bn2_v,
        proj_w, proj_b, emb, tokp);

    for (int l = 0; l < Lln; l++) {
        gemm_kernel<<<dim3(244, 6), 256, GEMM_SMEM>>>(
            tokp, qkv_w + l*3*Dn*Dn, qkv_b + l*3*Dn, qkvp, Dn, 3*Dn, 0);
        attn_kernel<<<Bn*Hn, 128, ATTN_SMEM>>>(qkvp, ctxp);
        gemm_ln_kernel<<<244, 256, GLN_SMEM128>>>(
            ctxp, out_w + l*Dn*Dn, out_b + l*Dn,
            tokp, ln1_g + l*Dn, ln1_b + l*Dn, tokp, Dn);
        gemm_kernel<<<dim3(244, 4), 256, GEMM_SMEM>>>(
            tokp, ff1_w + l*FFn*Dn, ff1_b + l*FFn, ffp, Dn, FFn, 1);
        gemm_ln_kernel<<<244, 256, GLN_SMEM256>>>(
            ffp, ff2_w + l*Dn*FFn, ff2_b + l*Dn,
            tokp, ln2_g + l*Dn, ln2_b + l*Dn, tokp, FFn);
    }

    head_kernel<<<Bn, 128>>>(tokp, sid, heads_w, heads_b, (float*)d_out);
}

// round 14
// speedup vs baseline: 1.0458x; 1.0458x over previous
#include <cuda_runtime.h>
#include <cuda_fp16.h>

#define Bn   64
#define Cn   122
#define Tn   500
#define COn  64
#define Dn   128
#define Hn   8
#define FFn  256
#define Lln  2
#define BC   (Bn*Cn)
#define EPSf 1e-5f

typedef unsigned long long ull;
typedef unsigned int uint32;

/* ---------------- scratch (device globals; no allocation) ---------------- */
__device__ float g_tok[BC*Dn];
__device__ float g_qkv[BC*3*Dn];
__device__ float g_ctx[BC*Dn];
__device__ float g_ff [BC*FFn];
__device__ uint32 g_UH[8*2304];   /* transformed conv2 weights, [p][64co][36] */
__device__ uint32 g_UL[8*2304];

/* Winograd F(4,5) matrices, points {0,1,-1,2,-2,1/2,-1/2,inf}.
   Verified (R13 passed, rel_err 3.3e-7). */
__device__ const float c_BT[8][8] = {
 {-1.f, 0.f, 5.25f, 0.f, -5.25f, 0.f, 1.f, 0.f},
 {0.f, 1.f, 1.f, -4.25f, -4.25f, 1.f, 1.f, 0.f},
 {0.f, -1.f, 1.f, 4.25f, -4.25f, -1.f, 1.f, 0.f},
 {0.f, 0.5f, 0.25f, -2.5f, -1.25f, 2.f, 1.f, 0.f},
 {0.f, -0.5f, 0.25f, 2.5f, -1.25f, -2.f, 1.f, 0.f},
 {0.f, 2.f, 4.f, -2.5f, -5.f, 0.5f, 1.f, 0.f},
 {0.f, -2.f, 4.f, 2.5f, -5.f, -0.5f, 1.f, 0.f},
 {0.f, -1.f, 0.f, 5.25f, 0.f, -5.25f, 0.f, 1.f}};
__device__ const float c_G32[8][5] = {
 {-32.f, 0.f, 0.f, 0.f, 0.f},
 {-7.1111111f, -7.1111111f, -7.1111111f, -7.1111111f, -7.1111111f},
 {-7.1111111f, 7.1111111f, -7.1111111f, 7.1111111f, -7.1111111f},
 {0.35555556f, 0.71111111f, 1.42222222f, 2.84444444f, 5.68888889f},
 {0.35555556f, -0.71111111f, 1.42222222f, -2.84444444f, 5.68888889f},
 {22.7555556f, 11.3777778f, 5.68888889f, 2.84444444f, 1.42222222f},
 {22.7555556f, -11.3777778f, 5.68888889f, -2.84444444f, 1.42222222f},
 {0.f, 0.f, 0.f, 0.f, 32.f}};
__device__ const float c_AT[4][8] = {
 {1.f, 1.f, 1.f, 1.f, 1.f, 1.f, 1.f, 0.f},
 {0.f, 1.f, -1.f, 2.f, -2.f, 0.5f, -0.5f, 0.f},
 {0.f, 1.f, 1.f, 4.f, 4.f, 0.25f, 0.25f, 0.f},
 {0.f, 1.f, -1.f, 8.f, -8.f, 0.125f, -0.125f, 1.f}};

/* fast erf-GELU: Abramowitz-Stegun 7.1.26, |erf err| <= 1.5e-7 */
__device__ __forceinline__ float gelu_f(float x){
    float z  = fabsf(x) * 0.70710678118654752440f;
    float t  = __fdividef(1.0f, 1.0f + 0.3275911f*z);
    float poly = t*(0.254829592f + t*(-0.284496736f +
                 t*(1.421413741f + t*(-1.453152027f + t*1.061405429f))));
    float erfz = 1.0f - poly*__expf(-z*z);
    float s = copysignf(erfz, x);
    return 0.5f*x*(1.0f + s);
}

/* packed f32x2 helpers (transformer GEMMs) */
__device__ __forceinline__ ull pk(float a, float b){
    ull r; asm("mov.b64 %0, {%1, %2};" : "=l"(r) : "f"(a), "f"(b)); return r;
}
__device__ __forceinline__ void fma2(ull& d, ull a, ull b){
    asm("fma.rn.f32x2 %0, %1, %2, %0;" : "+l"(d) : "l"(a), "l"(b));
}
__device__ __forceinline__ float2 upk(ull a){
    float2 f; asm("mov.b64 {%0, %1}, %2;" : "=f"(f.x), "=f"(f.y) : "l"(a)); return f;
}

/* fp16 mma m16n8k16, fp32 accum */
__device__ __forceinline__ void mma_f16(float* c,
    uint32 a0, uint32 a1, uint32 a2, uint32 a3, uint32 b0, uint32 b1){
    asm volatile("mma.sync.aligned.m16n8k16.row.col.f32.f16.f16.f32 "
        "{%0,%1,%2,%3}, {%4,%5,%6,%7}, {%8,%9}, {%0,%1,%2,%3};"
        : "+f"(c[0]), "+f"(c[1]), "+f"(c[2]), "+f"(c[3])
        : "r"(a0), "r"(a1), "r"(a2), "r"(a3), "r"(b0), "r"(b1));
}

__device__ __forceinline__ uint32 h2pack(__half lo, __half hi){
    __half2 h = __halves2half2(lo, hi);
    return *(uint32*)&h;
}

/* ============================================================
   Kernel 0: one-time Winograd weight transform (sample-invariant).
   U_p[co][q] = (32*G_p*w)[co][ci-pair q], hi/lo fp16, layout [64][36].
   ============================================================ */
__global__ void uprep_kernel(const float* __restrict__ w2)
{
    const int p = blockIdx.x;
    float gg[5];
    #pragma unroll
    for (int k = 0; k < 5; k++) gg[k] = c_G32[p][k];
    for (int idx = threadIdx.x; idx < 64*32; idx += 256) {
        int co = idx >> 5, q = idx & 31;
        const float* wp0 = &w2[co*320 + (2*q)*5];
        float u0 = 0.f, u1 = 0.f;
        #pragma unroll
        for (int k = 0; k < 5; k++) {
            u0 += gg[k]*wp0[k];
            u1 += gg[k]*wp0[5 + k];
        }
        __half h0 = __float2half_rn(u0);
        __half h1v = __float2half_rn(u1);
        __half l0 = __float2half_rn(u0 - __half2float(h0));
        __half l1 = __float2half_rn(u1 - __half2float(h1v));
        g_UH[p*2304 + co*36 + q] = h2pack(h0, h1v);
        g_UL[p*2304 + co*36 + q] = h2pack(l0, l1);
    }
}

/* SMEM layout (bytes):
   V_all @0: 8 planes x [32 cipair][72] uint32, hi then lo interleaved by plane:
     VH plane p @ p*9216, VL plane p @ 73728 + p*9216          147456
   sh1f  @147456  float[64*264]  67584   (dead after V build)
     UHs @147456 uint32[2304]  9216   (aliases sh1f, used in point loop)
     ULs @156672 uint32[2304]  9216
   sx    @215040  float[512]
   sw1   @217088  float[576]
   sAB   @219392  4 x float[64]
   spart @220416  float[64]
   sh2   @220672  float[64]
   total 220928 */
#define VH_OFF    0
#define VL_OFF    73728
#define SH1_OFF   147456
#define UHS_OFF   147456
#define ULS_OFF   156672
#define SX_OFF    215040
#define SW1_OFF   217088
#define SAB_OFF   219392
#define SPART_OFF 220416
#define SH2_OFF   220672
#define CONV_SMEM 220928

/* ============================================================
   Kernel 1: per-(b,c) fused conv pipeline, 512 threads, Winograd F(4,5).
   V built for ALL 8 points in one pass (window read once);
   U loaded per point from precomputed globals (L2-resident).
   ============================================================ */
__global__ void __launch_bounds__(512, 1) conv_kernel(
    const float* __restrict__ x,
    const float* __restrict__ w1, const float* __restrict__ cb1,
    const float* __restrict__ g1, const float* __restrict__ be1,
    const float* __restrict__ m1, const float* __restrict__ v1,
    const float* __restrict__ cb2,
    const float* __restrict__ g2, const float* __restrict__ be2,
    const float* __restrict__ m2, const float* __restrict__ v2,
    const float* __restrict__ pw, const float* __restrict__ pb,
    const float* __restrict__ emb, float* __restrict__ tok)
{
    extern __shared__ char smraw[];
    uint32* Vbase = (uint32*)(smraw + VH_OFF);
    float*  sh1f  = (float*)(smraw + SH1_OFF);
    uint32* UHs   = (uint32*)(smraw + UHS_OFF);
    uint32* ULs   = (uint32*)(smraw + ULS_OFF);
    float*  sx    = (float*)(smraw + SX_OFF);
    float*  sw1   = (float*)(smraw + SW1_OFF);
    float*  sA1   = (float*)(smraw + SAB_OFF);
    float*  sB1   = sA1 + 64;
    float*  sA2   = sA1 + 128;
    float*  sB2   = sA1 + 192;
    float*  spart = (float*)(smraw + SPART_OFF);
    float*  sh2   = (float*)(smraw + SH2_OFF);

    const int bc  = blockIdx.x;
    const int tid = threadIdx.x;
    const int wid = tid >> 5, lane = tid & 31;
    const int g   = lane >> 2, t4 = lane & 3;
    const int mc  = wid & 3,  tc  = wid >> 2;    /* 4x4 warp grid */

    /* ---- phase 0 ---- */
    {
        int t = tid - 4;
        sx[tid] = (t >= 0 && t < Tn) ? x[bc*Tn + t] : 0.f;
    }
    for (int i = tid; i < COn*9; i += 512) sw1[i] = w1[i];
    if (tid < 64) {
        float a1 = g1[tid]*rsqrtf(v1[tid]+EPSf);
        sA1[tid] = a1;  sB1[tid] = (cb1[tid]-m1[tid])*a1 + be1[tid];
        float a2 = g2[tid]*rsqrtf(v2[tid]+EPSf);
        sA2[tid] = a2;  sB2[tid] = (cb2[tid]-m2[tid])*a2 + be2[tid];
        spart[tid] = 0.f;
    }
    /* zero sh1 pad cols {0,1} U [252,264) */
    for (int i = tid; i < 64*14; i += 512) {
        int row = i / 14, j = i - row*14;
        int col = (j < 2) ? j : (250 + j);
        sh1f[row*264 + col] = 0.f;
    }
    __syncthreads();

    /* ---- conv1 + BN + GELU + maxpool(2) -> sh1f fp32 ---- */
    for (int i = tid; i < COn*250; i += 512) {
        int co = i / 250; int tp = i - co*250;
        const float* wp = &sw1[co*9];
        const float* xp = &sx[2*tp];
        float a0 = 0.f, a1 = 0.f;
        #pragma unroll
        for (int k = 0; k < 9; k++) { a0 += xp[k]*wp[k]; a1 += xp[k+1]*wp[k]; }
        float A = sA1[co], Bv = sB1[co];
        float y0 = gelu_f(a0*A + Bv);
        float y1 = gelu_f(a1*A + Bv);
        sh1f[co*264 + 2 + tp] = fmaxf(y0, y1);
    }
    __syncthreads();

    /* ---- V build: ALL 8 points per window read ---- */
    for (int idx = tid; idx < 32*64; idx += 512) {
        int cp = idx >> 6, tile = idx & 63;
        const float* r0 = &sh1f[(2*cp)*264 + 4*tile];
        const float* r1 = r0 + 264;
        float4 q0 = *(const float4*)r0;
        float4 q1 = *(const float4*)(r0 + 4);
        float4 s0 = *(const float4*)r1;
        float4 s1 = *(const float4*)(r1 + 4);
        float h0[8] = {q0.x,q0.y,q0.z,q0.w, q1.x,q1.y,q1.z,q1.w};
        float h1[8] = {s0.x,s0.y,s0.z,s0.w, s1.x,s1.y,s1.z,s1.w};
        #pragma unroll
        for (int p = 0; p < 8; p++) {
            float v0 = 0.f, v1 = 0.f;
            #pragma unroll
            for (int j = 0; j < 8; j++) {
                float b = c_BT[p][j];
                v0 += b*h0[j];
                v1 += b*h1[j];
            }
            __half hh0 = __float2half_rn(v0);
            __half hh1 = __float2half_rn(v1);
            __half ll0 = __float2half_rn(v0 - __half2float(hh0));
            __half ll1 = __float2half_rn(v1 - __half2float(hh1));
            Vbase[p*2304 + cp*72 + tile]         = h2pack(hh0, hh1);
            Vbase[18432 + p*2304 + cp*72 + tile] = h2pack(ll0, ll1);
        }
    }
    __syncthreads();
    /* sh1f is now dead; UHs/ULs alias it */

    /* ---- point loop: U copy + GEMM_p ---- */
    float y_acc[2][4][4];
    #pragma unroll
    for (int nj = 0; nj < 2; nj++)
        #pragma unroll
        for (int r = 0; r < 4; r++)
            #pragma unroll
            for (int i = 0; i < 4; i++) y_acc[nj][r][i] = 0.f;

    for (int p = 0; p < 8; p++) {
        for (int i = tid; i < 2304; i += 512) {
            UHs[i] = g_UH[p*2304 + i];
            ULs[i] = g_UL[p*2304 + i];
        }
        __syncthreads();

        const uint32* VHp = Vbase + p*2304;
        const uint32* VLp = Vbase + 18432 + p*2304;

        float acc[2][4];
        #pragma unroll
        for (int nj = 0; nj < 2; nj++)
            #pragma unroll
            for (int r = 0; r < 4; r++) acc[nj][r] = 0.f;

        #pragma unroll
        for (int s = 0; s < 4; s++) {
            int q0 = s*8 + t4;
            int ra  = (mc*16 + g)*36 + q0;
            int rb2 = ra + 8*36;
            uint32 aH0 = UHs[ra],   aH1 = UHs[rb2];
            uint32 aH2 = UHs[ra+4], aH3 = UHs[rb2+4];
            uint32 aL0 = ULs[ra],   aL1 = ULs[rb2];
            uint32 aL2 = ULs[ra+4], aL3 = ULs[rb2+4];
            #pragma unroll
            for (int nj = 0; nj < 2; nj++) {
                int n  = tc*16 + nj*8 + g;
                int rv = (s*8 + t4)*72 + n;
                uint32 bh0 = VHp[rv], bh1 = VHp[rv + 4*72];
                uint32 bl0 = VLp[rv], bl1 = VLp[rv + 4*72];
                mma_f16(acc[nj], aH0, aH1, aH2, aH3, bh0, bh1);
                mma_f16(acc[nj], aL0, aL1, aL2, aL3, bh0, bh1);
                mma_f16(acc[nj], aH0, aH1, aH2, aH3, bl0, bl1);
            }
        }

        float at[4];
        #pragma unroll
        for (int i = 0; i < 4; i++) at[i] = c_AT[i][p];
        #pragma unroll
        for (int nj = 0; nj < 2; nj++)
            #pragma unroll
            for (int r = 0; r < 4; r++) {
                float m = acc[nj][r];
                #pragma unroll
                for (int i = 0; i < 4; i++) y_acc[nj][r][i] += at[i]*m;
            }
        __syncthreads();
    }

    /* ---- epilogue: BN + GELU + mean partials (verified R13) ---- */
    {
        const int co0 = mc*16 + g, co1 = co0 + 8;
        const float A0 = sA2[co0]*(1.0f/32.0f), B0 = sB2[co0];
        const float A1 = sA2[co1]*(1.0f/32.0f), B1 = sB2[co1];
        float s0 = 0.f, s1 = 0.f;
        #pragma unroll
        for (int nj = 0; nj < 2; nj++) {
            #pragma unroll
            for (int r = 0; r < 4; r++) {
                int tile = tc*16 + nj*8 + 2*t4 + (r & 1);
                float A = (r < 2) ? A0 : A1;
                float Bv = (r < 2) ? B0 : B1;
                #pragma unroll
                for (int i = 0; i < 4; i++) {
                    int t = 4*tile + i;
                    if (t < 250) {
                        float v = gelu_f(y_acc[nj][r][i]*A + Bv);
                        if (r < 2) s0 += v; else s1 += v;
                    }
                }
            }
        }
        s0 += __shfl_xor_sync(0xffffffffu, s0, 1);
        s0 += __shfl_xor_sync(0xffffffffu, s0, 2);
        s1 += __shfl_xor_sync(0xffffffffu, s1, 1);
        s1 += __shfl_xor_sync(0xffffffffu, s1, 2);
        if (t4 == 0) {
            atomicAdd(&spart[co0], s0);
            atomicAdd(&spart[co1], s1);
        }
    }
    __syncthreads();
    if (tid < 64) sh2[tid] = spart[tid] * (1.f/250.f);
    __syncthreads();

    /* proj + elec_emb -> tok */
    if (tid < 128) {
        const int d = tid;
        float acc2 = pb[d];
        const float* pwr = &pw[d*COn];
        #pragma unroll 8
        for (int c = 0; c < 64; c++) acc2 += sh2[c]*__ldg(&pwr[c]);
        int cidx = bc % Cn;
        tok[bc*Dn + d] = acc2 + emb[cidx*Dn + d];
    }
}

/* ============================================================
   Kernel 2: tiled GEMM  Y[M,N] = act(X[M,K] @ W[N,K]^T + bias)
   ============================================================ */
__global__ __launch_bounds__(256) void gemm_kernel(
    const float* __restrict__ X, const float* __restrict__ W,
    const float* __restrict__ bias, float* __restrict__ Y,
    int K, int N, int actGelu)
{
    extern __shared__ float sm[];
    float* sxT = sm;            /* [K][40] */
    float* swt = sm + K*40;     /* [K][65] */
    const int row0 = blockIdx.x*32;
    const int e0   = blockIdx.y*64;
    const int tid  = threadIdx.x;

    for (int li = tid; li < 32*K; li += 256) {
        int r = li / K, d = li - r*K;
        sxT[d*40 + r] = X[(row0+r)*K + d];
    }
    for (int li = tid; li < 64*K; li += 256) {
        int e = li / K, d = li - e*K;
        swt[d*65 + e] = W[(e0+e)*K + d];
    }
    __syncthreads();

    const int e_local = tid & 63, tg = tid >> 6;
    float bb = bias[e0 + e_local];
    ull acc[4];
    #pragma unroll
    for (int j = 0; j < 4; j++) acc[j] = pk(bb, bb);
    #pragma unroll 4
    for (int d = 0; d < K; d++) {
        ull Wp = pk(swt[d*65 + e_local], swt[d*65 + e_local]);
        const ull* tp = (const ull*)&sxT[d*40 + tg*8];
        fma2(acc[0], Wp, tp[0]);
        fma2(acc[1], Wp, tp[1]);
        fma2(acc[2], Wp, tp[2]);
        fma2(acc[3], Wp, tp[3]);
    }
    #pragma unroll
    for (int j = 0; j < 4; j++) {
        float2 y = upk(acc[j]);
        if (actGelu) { y.x = gelu_f(y.x); y.y = gelu_f(y.y); }
        Y[(row0 + tg*8 + 2*j  )*N + e0 + e_local] = y.x;
        Y[(row0 + tg*8 + 2*j+1)*N + e0 + e_local] = y.y;
    }
}

/* ============================================================
   Kernel 3: GEMM (N=128) + residual + LayerNorm epilogue
   ============================================================ */
__global__ __launch_bounds__(256) void gemm_ln_kernel(
    const float* __restrict__ X, const float* __restrict__ W,
    const float* __restrict__ bias,
    const float* __restrict__ Res,
    const float* __restrict__ lng, const float* __restrict__ lnb,
    float* __restrict__ Out, int K)
{
    extern __shared__ float sm[];
    float* sxT = sm;               /* [K][40]  */
    float* swt = sm + K*40;        /* [K][65]  */
    float* sy  = swt + K*65;       /* [32][132] */
    const int row0 = blockIdx.x*32;
    const int tid  = threadIdx.x;

    for (int li = tid; li < 32*K; li += 256) {
        int r = li / K, d = li - r*K;
        sxT[d*40 + r] = X[(row0+r)*K + d];
    }
    const int e_local = tid & 63, tg = tid >> 6;

    for (int e0 = 0; e0 < 128; e0 += 64) {
        __syncthreads();
        for (int li = tid; li < 64*K; li += 256) {
            int e = li / K, d = li - e*K;
            swt[d*65 + e] = W[(e0+e)*K + d];
        }
        __syncthreads();
        float bb = bias[e0 + e_local];
        ull acc[4];
        #pragma unroll
        for (int j = 0; j < 4; j++) acc[j] = pk(bb, bb);
        #pragma unroll 4
        for (int d = 0; d < K; d++) {
            ull Wp = pk(swt[d*65 + e_local], swt[d*65 + e_local]);
            const ull* tp = (const ull*)&sxT[d*40 + tg*8];
            fma2(acc[0], Wp, tp[0]);
            fma2(acc[1], Wp, tp[1]);
            fma2(acc[2], Wp, tp[2]);
            fma2(acc[3], Wp, tp[3]);
        }
        #pragma unroll
        for (int j = 0; j < 4; j++) {
            float2 y = upk(acc[j]);
            sy[(tg*8 + 2*j  )*132 + e0 + e_local] = y.x;
            sy[(tg*8 + 2*j+1)*132 + e0 + e_local] = y.y;
        }
    }
    __syncthreads();

    const int w = tid >> 5, lane = tid & 31;
    for (int q = 0; q < 4; q++) {
        int r = w*4 + q;
        float z[4]; float s1 = 0.f, s2 = 0.f;
        #pragma unroll
        for (int i = 0; i < 4; i++) {
            int idx = lane + 32*i;
            float zz = sy[r*132 + idx] + Res[(row0+r)*128 + idx];
            z[i] = zz; s1 += zz; s2 += zz*zz;
        }
        #pragma unroll
        for (int o = 16; o > 0; o >>= 1) {
            s1 += __shfl_xor_sync(0xffffffffu, s1, o);
            s2 += __shfl_xor_sync(0xffffffffu, s2, o);
        }
        float mean = s1*(1.f/128.f);
        float var  = s2*(1.f/128.f) - mean*mean;
        float rs   = rsqrtf(var + EPSf);
        #pragma unroll
        for (int i = 0; i < 4; i++) {
            int idx = lane + 32*i;
            Out[(row0+r)*128 + idx] = (z[i]-mean)*rs*lng[idx] + lnb[idx];
        }
    }
}

/* ============================================================
   Kernel 4: attention per (b, head). seq=122, dh=16.
   ============================================================ */
__global__ __launch_bounds__(128) void attn_kernel(
    const float* __restrict__ qkv, float* __restrict__ ctx)
{
    const int b = blockIdx.x >> 3, h = blockIdx.x & 7;
    extern __shared__ float sm[];
    float* sq = sm;                 /* [122][17] */
    float* sk = sm + 122*17;
    float* sv = sm + 2*122*17;
    float* sattb = sm + 3*122*17;   /* [4][128] */
    const int tid = threadIdx.x;

    for (int li = tid; li < 122*16; li += 128) {
        int s = li >> 4, d = li & 15;
        int base = (b*Cn + s)*384 + h*16 + d;
        sq[s*17 + d] = qkv[base];
        sk[s*17 + d] = qkv[base + 128];
        sv[s*17 + d] = qkv[base + 256];
    }
    __syncthreads();

    const int w = tid >> 5, lane = tid & 31;
    float* satt = sattb + w*128;

    for (int i = w; i < Cn; i += 4) {
        float sc[4];
        #pragma unroll
        for (int c = 0; c < 4; c++) {
            int kk = lane + 32*c;
            if (kk < Cn) {
                float s = 0.f;
                #pragma unroll
                for (int d = 0; d < 16; d++) s += sq[i*17 + d]*sk[kk*17 + d];
                sc[c] = s*0.25f;
            } else sc[c] = -1e30f;
        }
        float mx = fmaxf(fmaxf(sc[0], sc[1]), fmaxf(sc[2], sc[3]));
        #pragma unroll
        for (int o = 16; o > 0; o >>= 1) mx = fmaxf(mx, __shfl_xor_sync(0xffffffffu, mx, o));
        float p[4]; float sum = 0.f;
        #pragma unroll
        for (int c = 0; c < 4; c++) {
            int kk = lane + 32*c;
            p[c] = (kk < Cn) ? __expf(sc[c]-mx) : 0.f;
            sum += p[c];
        }
        #pragma unroll
        for (int o = 16; o > 0; o >>= 1) sum += __shfl_xor_sync(0xffffffffu, sum, o);
        float inv = __fdividef(1.f, sum);
        #pragma unroll
        for (int c = 0; c < 4; c++) {
            int kk = lane + 32*c;
            if (kk < Cn) satt[kk] = p[c]*inv;
        }
        __syncwarp();
        int d = lane & 15, half = lane >> 4;
        float a = 0.f;
        int j0 = half*61;
        for (int j = j0; j < j0 + 61; j++) a += satt[j]*sv[j*17 + d];
        a += __shfl_xor_sync(0xffffffffu, a, 16);
        if (lane < 16) ctx[(b*Cn + i)*Dn + h*16 + d] = a;
        __syncwarp();
    }
}

/* ============================================================
   Kernel 5: mean over C + per-subject head -> out[64,4]
   ============================================================ */
__global__ __launch_bounds__(128) void head_kernel(
    const float* __restrict__ tok, const int* __restrict__ sid,
    const float* __restrict__ hw, const float* __restrict__ hb,
    float* __restrict__ out)
{
    const int b = blockIdx.x;
    __shared__ float sp[128];
    const int d = threadIdx.x;
    float s = 0.f;
    for (int c = 0; c < Cn; c++) s += tok[(b*Cn + c)*Dn + d];
    sp[d] = s*(1.f/(float)Cn);
    __syncthreads();
    const int cls = threadIdx.x >> 5, lane = threadIdx.x & 31;
    const int sb = sid[b];
    float a = 0.f;
    #pragma unroll
    for (int i = 0; i < 4; i++) {
        int dd = lane + 32*i;
        a += sp[dd]*hw[(sb*4 + cls)*Dn + dd];
    }
    #pragma unroll
    for (int o = 16; o > 0; o >>= 1) a += __shfl_xor_sync(0xffffffffu, a, o);
    if (lane == 0) out[b*4 + cls] = a + hb[sb*4 + cls];
}

/* ============================================================ */
extern "C" void kernel_launch(void* const* d_in, const int* in_sizes, int n_in,
                              void* d_out, int out_size)
{
    const float* x       = (const float*)d_in[0];
    const int*   sid     = (const int*  )d_in[1];
    const float* conv1_w = (const float*)d_in[2];
    const float* conv1_b = (const float*)d_in[3];
    const float* bn1_g   = (const float*)d_in[4];
    const float* bn1_b   = (const float*)d_in[5];
    const float* bn1_m   = (const float*)d_in[6];
    const float* bn1_v   = (const float*)d_in[7];
    const float* conv2_w = (const float*)d_in[8];
    const float* conv2_b = (const float*)d_in[9];
    const float* bn2_g   = (const float*)d_in[10];
    const float* bn2_b   = (const float*)d_in[11];
    const float* bn2_m   = (const float*)d_in[12];
    const float* bn2_v   = (const float*)d_in[13];
    const float* proj_w  = (const float*)d_in[14];
    const float* proj_b  = (const float*)d_in[15];
    const float* emb     = (const float*)d_in[16];
    const float* qkv_w   = (const float*)d_in[17];
    const float* qkv_b   = (const float*)d_in[18];
    const float* out_w   = (const float*)d_in[19];
    const float* out_b   = (const float*)d_in[20];
    const float* ln1_g   = (const float*)d_in[21];
    const float* ln1_b   = (const float*)d_in[22];
    const float* ff1_w   = (const float*)d_in[23];
    const float* ff1_b   = (const float*)d_in[24];
    const float* ff2_w   = (const float*)d_in[25];
    const float* ff2_b   = (const float*)d_in[26];
    const float* ln2_g   = (const float*)d_in[27];
    const float* ln2_b   = (const float*)d_in[28];
    const float* heads_w = (const float*)d_in[29];
    const float* heads_b = (const float*)d_in[30];

    const int GEMM_SMEM   = (128*40 + 128*65)*4;           /* 53760 B  */
    const int GLN_SMEM128 = (128*40 + 128*65 + 32*132)*4;  /* 70656 B  */
    const int GLN_SMEM256 = (256*40 + 256*65 + 32*132)*4;  /* 124416 B */
    const int ATTN_SMEM   = (3*122*17 + 4*128)*4;          /* 26936 B  */

    cudaFuncSetAttribute(conv_kernel,    cudaFuncAttributeMaxDynamicSharedMemorySize, CONV_SMEM);
    cudaFuncSetAttribute(gemm_kernel,    cudaFuncAttributeMaxDynamicSharedMemorySize, GEMM_SMEM);
    cudaFuncSetAttribute(gemm_ln_kernel, cudaFuncAttributeMaxDynamicSharedMemorySize, GLN_SMEM256);

    float* tokp = nullptr; float* qkvp = nullptr; float* ctxp = nullptr; float* ffp = nullptr;
    cudaGetSymbolAddress((void**)&tokp, g_tok);
    cudaGetSymbolAddress((void**)&qkvp, g_qkv);
    cudaGetSymbolAddress((void**)&ctxp, g_ctx);
    cudaGetSymbolAddress((void**)&ffp,  g_ff);

    uprep_kernel<<<8, 256>>>(conv2_w);

    conv_kernel<<<BC, 512, CONV_SMEM>>>(
        x, conv1_w, conv1_b, bn1_g, bn1_b, bn1_m, bn1_v,
        conv2_b, bn2_g, bn2_b, bn2_m, bn2_v,
        proj_w, proj_b, emb, tokp);

    for (int l = 0; l < Lln; l++) {
        gemm_kernel<<<dim3(244, 6), 256, GEMM_SMEM>>>(
            tokp, qkv_w + l*3*Dn*Dn, qkv_b + l*3*Dn, qkvp, Dn, 3*Dn, 0);
        attn_kernel<<<Bn*Hn, 128, ATTN_SMEM>>>(qkvp, ctxp);
        gemm_ln_kernel<<<244, 256, GLN_SMEM128>>>(
            ctxp, out_w + l*Dn*Dn, out_b + l*Dn,
            tokp, ln1_g + l*Dn, ln1_b + l*Dn, tokp, Dn);
        gemm_kernel<<<dim3(244, 4), 256, GEMM_SMEM>>>(
            tokp, ff1_w + l*FFn*Dn, ff1_b + l*FFn, ffp, Dn, FFn, 1);
        gemm_ln_kernel<<<244, 256, GLN_SMEM256>>>(
            ffp, ff2_w + l*Dn*FFn, ff2_b + l*Dn,
            tokp, ln2_g + l*Dn, ln2_b + l*Dn, tokp, FFn);
    }

    head_kernel<<<Bn, 128>>>(tokp, sid, heads_w, heads_b, (float*)d_out);
}

// round 15
// speedup vs baseline: 1.0894x; 1.0417x over previous
#include <cuda_runtime.h>
#include <cuda_fp16.h>

#define Bn   64
#define Cn   122
#define Tn   500
#define COn  64
#define Dn   128
#define Hn   8
#define FFn  256
#define Lln  2
#define BC   (Bn*Cn)
#define EPSf 1e-5f

typedef unsigned long long ull;
typedef unsigned int uint32;

/* ---------------- scratch (device globals; no allocation) ---------------- */
__device__ float g_tok[BC*Dn];
__device__ float g_qkv[BC*3*Dn];
__device__ float g_ctx[BC*Dn];
__device__ float g_ff [BC*FFn];
__device__ uint32 g_UH[8*2304];   /* transformed conv2 weights, [p][64co][36] */
__device__ uint32 g_UL[8*2304];

/* Winograd F(4,5) matrices, points {0,1,-1,2,-2,1/2,-1/2,inf}.
   Verified (R13/R14 passed, rel_err 3.3e-7). */
__device__ const float c_BT[8][8] = {
 {-1.f, 0.f, 5.25f, 0.f, -5.25f, 0.f, 1.f, 0.f},
 {0.f, 1.f, 1.f, -4.25f, -4.25f, 1.f, 1.f, 0.f},
 {0.f, -1.f, 1.f, 4.25f, -4.25f, -1.f, 1.f, 0.f},
 {0.f, 0.5f, 0.25f, -2.5f, -1.25f, 2.f, 1.f, 0.f},
 {0.f, -0.5f, 0.25f, 2.5f, -1.25f, -2.f, 1.f, 0.f},
 {0.f, 2.f, 4.f, -2.5f, -5.f, 0.5f, 1.f, 0.f},
 {0.f, -2.f, 4.f, 2.5f, -5.f, -0.5f, 1.f, 0.f},
 {0.f, -1.f, 0.f, 5.25f, 0.f, -5.25f, 0.f, 1.f}};
__device__ const float c_G32[8][5] = {
 {-32.f, 0.f, 0.f, 0.f, 0.f},
 {-7.1111111f, -7.1111111f, -7.1111111f, -7.1111111f, -7.1111111f},
 {-7.1111111f, 7.1111111f, -7.1111111f, 7.1111111f, -7.1111111f},
 {0.35555556f, 0.71111111f, 1.42222222f, 2.84444444f, 5.68888889f},
 {0.35555556f, -0.71111111f, 1.42222222f, -2.84444444f, 5.68888889f},
 {22.7555556f, 11.3777778f, 5.68888889f, 2.84444444f, 1.42222222f},
 {22.7555556f, -11.3777778f, 5.68888889f, -2.84444444f, 1.42222222f},
 {0.f, 0.f, 0.f, 0.f, 32.f}};
__device__ const float c_AT[4][8] = {
 {1.f, 1.f, 1.f, 1.f, 1.f, 1.f, 1.f, 0.f},
 {0.f, 1.f, -1.f, 2.f, -2.f, 0.5f, -0.5f, 0.f},
 {0.f, 1.f, 1.f, 4.f, 4.f, 0.25f, 0.25f, 0.f},
 {0.f, 1.f, -1.f, 8.f, -8.f, 0.125f, -0.125f, 1.f}};

/* fast erf-GELU: Abramowitz-Stegun 7.1.26, |erf err| <= 1.5e-7 */
__device__ __forceinline__ float gelu_f(float x){
    float z  = fabsf(x) * 0.70710678118654752440f;
    float t  = __fdividef(1.0f, 1.0f + 0.3275911f*z);
    float poly = t*(0.254829592f + t*(-0.284496736f +
                 t*(1.421413741f + t*(-1.453152027f + t*1.061405429f))));
    float erfz = 1.0f - poly*__expf(-z*z);
    float s = copysignf(erfz, x);
    return 0.5f*x*(1.0f + s);
}

/* packed f32x2 helpers (transformer GEMMs) */
__device__ __forceinline__ ull pk(float a, float b){
    ull r; asm("mov.b64 %0, {%1, %2};" : "=l"(r) : "f"(a), "f"(b)); return r;
}
__device__ __forceinline__ void fma2(ull& d, ull a, ull b){
    asm("fma.rn.f32x2 %0, %1, %2, %0;" : "+l"(d) : "l"(a), "l"(b));
}
__device__ __forceinline__ float2 upk(ull a){
    float2 f; asm("mov.b64 {%0, %1}, %2;" : "=f"(f.x), "=f"(f.y) : "l"(a)); return f;
}

/* fp16 mma m16n8k16, fp32 accum */
__device__ __forceinline__ void mma_f16(float* c,
    uint32 a0, uint32 a1, uint32 a2, uint32 a3, uint32 b0, uint32 b1){
    asm volatile("mma.sync.aligned.m16n8k16.row.col.f32.f16.f16.f32 "
        "{%0,%1,%2,%3}, {%4,%5,%6,%7}, {%8,%9}, {%0,%1,%2,%3};"
        : "+f"(c[0]), "+f"(c[1]), "+f"(c[2]), "+f"(c[3])
        : "r"(a0), "r"(a1), "r"(a2), "r"(a3), "r"(b0), "r"(b1));
}

__device__ __forceinline__ uint32 h2pack(__half lo, __half hi){
    __half2 h = __halves2half2(lo, hi);
    return *(uint32*)&h;
}

/* ============================================================
   Kernel 0: one-time Winograd weight transform (sample-invariant).
   ============================================================ */
__global__ void uprep_kernel(const float* __restrict__ w2)
{
    const int p = blockIdx.x;
    float gg[5];
    #pragma unroll
    for (int k = 0; k < 5; k++) gg[k] = c_G32[p][k];
    for (int idx = threadIdx.x; idx < 64*32; idx += 256) {
        int co = idx >> 5, q = idx & 31;
        const float* wp0 = &w2[co*320 + (2*q)*5];
        float u0 = 0.f, u1 = 0.f;
        #pragma unroll
        for (int k = 0; k < 5; k++) {
            u0 += gg[k]*wp0[k];
            u1 += gg[k]*wp0[5 + k];
        }
        __half h0 = __float2half_rn(u0);
        __half h1v = __float2half_rn(u1);
        __half l0 = __float2half_rn(u0 - __half2float(h0));
        __half l1 = __float2half_rn(u1 - __half2float(h1v));
        g_UH[p*2304 + co*36 + q] = h2pack(h0, h1v);
        g_UL[p*2304 + co*36 + q] = h2pack(l0, l1);
    }
}

/* SMEM layout (bytes):
   V_all @0: VH plane p @ p*9216, VL plane p @ 73728 + p*9216   147456
   sh1f  @147456  float[64*264]  67584   (dead after V build);
     U double buffers alias it:
     UH0 @147456  UL0 @156672  UH1 @165888  UL1 @175104   (36864 <= 67584)
   sx    @215040  float[512]
   sw1   @217088  float[576]
   sAB   @219392  4 x float[64]
   spart @220416  float[64]
   sh2   @220672  float[64]
   total 220928 */
#define VH_OFF    0
#define SH1_OFF   147456
#define UH0_OFF   147456
#define UL0_OFF   156672
#define UH1_OFF   165888
#define UL1_OFF   175104
#define SX_OFF    215040
#define SW1_OFF   217088
#define SAB_OFF   219392
#define SPART_OFF 220416
#define SH2_OFF   220672
#define CONV_SMEM 220928

/* ============================================================
   Kernel 1: per-(b,c) fused conv pipeline, 512 threads, Winograd F(4,5).
   V built for ALL 8 points in one pass; U double-buffered with
   register prefetch (LDG issued before the GEMM that hides it).
   ============================================================ */
__global__ void __launch_bounds__(512, 1) conv_kernel(
    const float* __restrict__ x,
    const float* __restrict__ w1, const float* __restrict__ cb1,
    const float* __restrict__ g1, const float* __restrict__ be1,
    const float* __restrict__ m1, const float* __restrict__ v1,
    const float* __restrict__ cb2,
    const float* __restrict__ g2, const float* __restrict__ be2,
    const float* __restrict__ m2, const float* __restrict__ v2,
    const float* __restrict__ pw, const float* __restrict__ pb,
    const float* __restrict__ emb, float* __restrict__ tok)
{
    extern __shared__ char smraw[];
    uint32* Vbase = (uint32*)(smraw + VH_OFF);
    float*  sh1f  = (float*)(smraw + SH1_OFF);
    uint32* UHb[2] = { (uint32*)(smraw + UH0_OFF), (uint32*)(smraw + UH1_OFF) };
    uint32* ULb[2] = { (uint32*)(smraw + UL0_OFF), (uint32*)(smraw + UL1_OFF) };
    float*  sx    = (float*)(smraw + SX_OFF);
    float*  sw1   = (float*)(smraw + SW1_OFF);
    float*  sA1   = (float*)(smraw + SAB_OFF);
    float*  sB1   = sA1 + 64;
    float*  sA2   = sA1 + 128;
    float*  sB2   = sA1 + 192;
    float*  spart = (float*)(smraw + SPART_OFF);
    float*  sh2   = (float*)(smraw + SH2_OFF);

    const int bc  = blockIdx.x;
    const int tid = threadIdx.x;
    const int wid = tid >> 5, lane = tid & 31;
    const int g   = lane >> 2, t4 = lane & 3;
    const int mc  = wid & 3,  tc  = wid >> 2;    /* 4x4 warp grid */

    /* ---- phase 0 ---- */
    {
        int t = tid - 4;
        sx[tid] = (t >= 0 && t < Tn) ? x[bc*Tn + t] : 0.f;
    }
    for (int i = tid; i < COn*9; i += 512) sw1[i] = w1[i];
    if (tid < 64) {
        float a1 = g1[tid]*rsqrtf(v1[tid]+EPSf);
        sA1[tid] = a1;  sB1[tid] = (cb1[tid]-m1[tid])*a1 + be1[tid];
        float a2 = g2[tid]*rsqrtf(v2[tid]+EPSf);
        sA2[tid] = a2;  sB2[tid] = (cb2[tid]-m2[tid])*a2 + be2[tid];
        spart[tid] = 0.f;
    }
    /* zero sh1 pad cols {0,1} U [252,264) */
    for (int i = tid; i < 64*14; i += 512) {
        int row = i / 14, j = i - row*14;
        int col = (j < 2) ? j : (250 + j);
        sh1f[row*264 + col] = 0.f;
    }
    __syncthreads();

    /* ---- conv1 + BN + GELU + maxpool(2) -> sh1f fp32 ---- */
    for (int i = tid; i < COn*250; i += 512) {
        int co = i / 250; int tp = i - co*250;
        const float* wp = &sw1[co*9];
        const float* xp = &sx[2*tp];
        float a0 = 0.f, a1 = 0.f;
        #pragma unroll
        for (int k = 0; k < 9; k++) { a0 += xp[k]*wp[k]; a1 += xp[k+1]*wp[k]; }
        float A = sA1[co], Bv = sB1[co];
        float y0 = gelu_f(a0*A + Bv);
        float y1 = gelu_f(a1*A + Bv);
        sh1f[co*264 + 2 + tp] = fmaxf(y0, y1);
    }
    __syncthreads();

    /* ---- V build: ALL 8 points per window read ---- */
    for (int idx = tid; idx < 32*64; idx += 512) {
        int cp = idx >> 6, tile = idx & 63;
        const float* r0 = &sh1f[(2*cp)*264 + 4*tile];
        const float* r1 = r0 + 264;
        float4 q0 = *(const float4*)r0;
        float4 q1 = *(const float4*)(r0 + 4);
        float4 s0 = *(const float4*)r1;
        float4 s1 = *(const float4*)(r1 + 4);
        float h0[8] = {q0.x,q0.y,q0.z,q0.w, q1.x,q1.y,q1.z,q1.w};
        float h1[8] = {s0.x,s0.y,s0.z,s0.w, s1.x,s1.y,s1.z,s1.w};
        #pragma unroll
        for (int p = 0; p < 8; p++) {
            float v0 = 0.f, v1 = 0.f;
            #pragma unroll
            for (int j = 0; j < 8; j++) {
                float b = c_BT[p][j];
                v0 += b*h0[j];
                v1 += b*h1[j];
            }
            __half hh0 = __float2half_rn(v0);
            __half hh1 = __float2half_rn(v1);
            __half ll0 = __float2half_rn(v0 - __half2float(hh0));
            __half ll1 = __float2half_rn(v1 - __half2float(hh1));
            Vbase[p*2304 + cp*72 + tile]         = h2pack(hh0, hh1);
            Vbase[18432 + p*2304 + cp*72 + tile] = h2pack(ll0, ll1);
        }
    }
    __syncthreads();
    /* sh1f now dead; load U for p=0 into buffer 0 */
    for (int i = tid; i < 2304; i += 512) {
        UHb[0][i] = g_UH[i];
        ULb[0][i] = g_UL[i];
    }
    __syncthreads();

    /* ---- point loop: prefetched double-buffered U + GEMM_p ---- */
    float y_acc[2][4][4];
    #pragma unroll
    for (int nj = 0; nj < 2; nj++)
        #pragma unroll
        for (int r = 0; r < 4; r++)
            #pragma unroll
            for (int i = 0; i < 4; i++) y_acc[nj][r][i] = 0.f;

    for (int p = 0; p < 8; p++) {
        const int cur = p & 1;
        /* prefetch U[p+1] into registers (hidden by the GEMM below) */
        uint32 rH[5], rL[5];
        if (p < 7) {
            #pragma unroll
            for (int k = 0; k < 5; k++) {
                int i = tid + k*512;
                if (i < 2304) {
                    rH[k] = g_UH[(p+1)*2304 + i];
                    rL[k] = g_UL[(p+1)*2304 + i];
                }
            }
        }

        const uint32* UHs = UHb[cur];
        const uint32* ULs = ULb[cur];
        const uint32* VHp = Vbase + p*2304;
        const uint32* VLp = Vbase + 18432 + p*2304;

        float acc[2][4];
        #pragma unroll
        for (int nj = 0; nj < 2; nj++)
            #pragma unroll
            for (int r = 0; r < 4; r++) acc[nj][r] = 0.f;

        #pragma unroll
        for (int s = 0; s < 4; s++) {
            int q0 = s*8 + t4;
            int ra  = (mc*16 + g)*36 + q0;
            int rb2 = ra + 8*36;
            uint32 aH0 = UHs[ra],   aH1 = UHs[rb2];
            uint32 aH2 = UHs[ra+4], aH3 = UHs[rb2+4];
            uint32 aL0 = ULs[ra],   aL1 = ULs[rb2];
            uint32 aL2 = ULs[ra+4], aL3 = ULs[rb2+4];
            #pragma unroll
            for (int nj = 0; nj < 2; nj++) {
                int n  = tc*16 + nj*8 + g;
                int rv = (s*8 + t4)*72 + n;
                uint32 bh0 = VHp[rv], bh1 = VHp[rv + 4*72];
                uint32 bl0 = VLp[rv], bl1 = VLp[rv + 4*72];
                mma_f16(acc[nj], aH0, aH1, aH2, aH3, bh0, bh1);
                mma_f16(acc[nj], aL0, aL1, aL2, aL3, bh0, bh1);
                mma_f16(acc[nj], aH0, aH1, aH2, aH3, bl0, bl1);
            }
        }

        float at[4];
        #pragma unroll
        for (int i = 0; i < 4; i++) at[i] = c_AT[i][p];
        #pragma unroll
        for (int nj = 0; nj < 2; nj++)
            #pragma unroll
            for (int r = 0; r < 4; r++) {
                float m = acc[nj][r];
                #pragma unroll
                for (int i = 0; i < 4; i++) y_acc[nj][r][i] += at[i]*m;
            }

        /* commit prefetched U[p+1] to the alternate buffer */
        if (p < 7) {
            #pragma unroll
            for (int k = 0; k < 5; k++) {
                int i = tid + k*512;
                if (i < 2304) {
                    UHb[cur^1][i] = rH[k];
                    ULb[cur^1][i] = rL[k];
                }
            }
        }
        __syncthreads();
    }

    /* ---- epilogue: BN + GELU + mean partials (verified R13/R14) ---- */
    {
        const int co0 = mc*16 + g, co1 = co0 + 8;
        const float A0 = sA2[co0]*(1.0f/32.0f), B0 = sB2[co0];
        const float A1 = sA2[co1]*(1.0f/32.0f), B1 = sB2[co1];
        float s0 = 0.f, s1 = 0.f;
        #pragma unroll
        for (int nj = 0; nj < 2; nj++) {
            #pragma unroll
            for (int r = 0; r < 4; r++) {
                int tile = tc*16 + nj*8 + 2*t4 + (r & 1);
                float A = (r < 2) ? A0 : A1;
                float Bv = (r < 2) ? B0 : B1;
                #pragma unroll
                for (int i = 0; i < 4; i++) {
                    int t = 4*tile + i;
                    if (t < 250) {
                        float v = gelu_f(y_acc[nj][r][i]*A + Bv);
                        if (r < 2) s0 += v; else s1 += v;
                    }
                }
            }
        }
        s0 += __shfl_xor_sync(0xffffffffu, s0, 1);
        s0 += __shfl_xor_sync(0xffffffffu, s0, 2);
        s1 += __shfl_xor_sync(0xffffffffu, s1, 1);
        s1 += __shfl_xor_sync(0xffffffffu, s1, 2);
        if (t4 == 0) {
            atomicAdd(&spart[co0], s0);
            atomicAdd(&spart[co1], s1);
        }
    }
    __syncthreads();
    if (tid < 64) sh2[tid] = spart[tid] * (1.f/250.f);
    __syncthreads();

    /* proj + elec_emb -> tok */
    if (tid < 128) {
        const int d = tid;
        float acc2 = pb[d];
        const float* pwr = &pw[d*COn];
        #pragma unroll 8
        for (int c = 0; c < 64; c++) acc2 += sh2[c]*__ldg(&pwr[c]);
        int cidx = bc % Cn;
        tok[bc*Dn + d] = acc2 + emb[cidx*Dn + d];
    }
}

/* ============================================================
   Kernel 2: tiled GEMM  Y[M,N] = act(X[M,K] @ W[N,K]^T + bias)
   ============================================================ */
__global__ __launch_bounds__(256) void gemm_kernel(
    const float* __restrict__ X, const float* __restrict__ W,
    const float* __restrict__ bias, float* __restrict__ Y,
    int K, int N, int actGelu)
{
    extern __shared__ float sm[];
    float* sxT = sm;            /* [K][40] */
    float* swt = sm + K*40;     /* [K][65] */
    const int row0 = blockIdx.x*32;
    const int e0   = blockIdx.y*64;
    const int tid  = threadIdx.x;

    for (int li = tid; li < 32*K; li += 256) {
        int r = li / K, d = li - r*K;
        sxT[d*40 + r] = X[(row0+r)*K + d];
    }
    for (int li = tid; li < 64*K; li += 256) {
        int e = li / K, d = li - e*K;
        swt[d*65 + e] = W[(e0+e)*K + d];
    }
    __syncthreads();

    const int e_local = tid & 63, tg = tid >> 6;
    float bb = bias[e0 + e_local];
    ull acc[4];
    #pragma unroll
    for (int j = 0; j < 4; j++) acc[j] = pk(bb, bb);
    #pragma unroll 4
    for (int d = 0; d < K; d++) {
        ull Wp = pk(swt[d*65 + e_local], swt[d*65 + e_local]);
        const ull* tp = (const ull*)&sxT[d*40 + tg*8];
        fma2(acc[0], Wp, tp[0]);
        fma2(acc[1], Wp, tp[1]);
        fma2(acc[2], Wp, tp[2]);
        fma2(acc[3], Wp, tp[3]);
    }
    #pragma unroll
    for (int j = 0; j < 4; j++) {
        float2 y = upk(acc[j]);
        if (actGelu) { y.x = gelu_f(y.x); y.y = gelu_f(y.y); }
        Y[(row0 + tg*8 + 2*j  )*N + e0 + e_local] = y.x;
        Y[(row0 + tg*8 + 2*j+1)*N + e0 + e_local] = y.y;
    }
}

/* ============================================================
   Kernel 3: GEMM (N=128) + residual + LayerNorm epilogue
   ============================================================ */
__global__ __launch_bounds__(256) void gemm_ln_kernel(
    const float* __restrict__ X, const float* __restrict__ W,
    const float* __restrict__ bias,
    const float* __restrict__ Res,
    const float* __restrict__ lng, const float* __restrict__ lnb,
    float* __restrict__ Out, int K)
{
    extern __shared__ float sm[];
    float* sxT = sm;               /* [K][40]  */
    float* swt = sm + K*40;        /* [K][65]  */
    float* sy  = swt + K*65;       /* [32][132] */
    const int row0 = blockIdx.x*32;
    const int tid  = threadIdx.x;

    for (int li = tid; li < 32*K; li += 256) {
        int r = li / K, d = li - r*K;
        sxT[d*40 + r] = X[(row0+r)*K + d];
    }
    const int e_local = tid & 63, tg = tid >> 6;

    for (int e0 = 0; e0 < 128; e0 += 64) {
        __syncthreads();
        for (int li = tid; li < 64*K; li += 256) {
            int e = li / K, d = li - e*K;
            swt[d*65 + e] = W[(e0+e)*K + d];
        }
        __syncthreads();
        float bb = bias[e0 + e_local];
        ull acc[4];
        #pragma unroll
        for (int j = 0; j < 4; j++) acc[j] = pk(bb, bb);
        #pragma unroll 4
        for (int d = 0; d < K; d++) {
            ull Wp = pk(swt[d*65 + e_local], swt[d*65 + e_local]);
            const ull* tp = (const ull*)&sxT[d*40 + tg*8];
            fma2(acc[0], Wp, tp[0]);
            fma2(acc[1], Wp, tp[1]);
            fma2(acc[2], Wp, tp[2]);
            fma2(acc[3], Wp, tp[3]);
        }
        #pragma unroll
        for (int j = 0; j < 4; j++) {
            float2 y = upk(acc[j]);
            sy[(tg*8 + 2*j  )*132 + e0 + e_local] = y.x;
            sy[(tg*8 + 2*j+1)*132 + e0 + e_local] = y.y;
        }
    }
    __syncthreads();

    const int w = tid >> 5, lane = tid & 31;
    for (int q = 0; q < 4; q++) {
        int r = w*4 + q;
        float z[4]; float s1 = 0.f, s2 = 0.f;
        #pragma unroll
        for (int i = 0; i < 4; i++) {
            int idx = lane + 32*i;
            float zz = sy[r*132 + idx] + Res[(row0+r)*128 + idx];
            z[i] = zz; s1 += zz; s2 += zz*zz;
        }
        #pragma unroll
        for (int o = 16; o > 0; o >>= 1) {
            s1 += __shfl_xor_sync(0xffffffffu, s1, o);
            s2 += __shfl_xor_sync(0xffffffffu, s2, o);
        }
        float mean = s1*(1.f/128.f);
        float var  = s2*(1.f/128.f) - mean*mean;
        float rs   = rsqrtf(var + EPSf);
        #pragma unroll
        for (int i = 0; i < 4; i++) {
            int idx = lane + 32*i;
            Out[(row0+r)*128 + idx] = (z[i]-mean)*rs*lng[idx] + lnb[idx];
        }
    }
}

/* ============================================================
   Kernel 4: attention per (b, head), 256 threads (8 query-warps).
   ============================================================ */
__global__ __launch_bounds__(256) void attn_kernel(
    const float* __restrict__ qkv, float* __restrict__ ctx)
{
    const int b = blockIdx.x >> 3, h = blockIdx.x & 7;
    extern __shared__ float sm[];
    float* sq = sm;                 /* [122][17] */
    float* sk = sm + 122*17;
    float* sv = sm + 2*122*17;
    float* sattb = sm + 3*122*17;   /* [8][128] */
    const int tid = threadIdx.x;

    for (int li = tid; li < 122*16; li += 256) {
        int s = li >> 4, d = li & 15;
        int base = (b*Cn + s)*384 + h*16 + d;
        sq[s*17 + d] = qkv[base];
        sk[s*17 + d] = qkv[base + 128];
        sv[s*17 + d] = qkv[base + 256];
    }
    __syncthreads();

    const int w = tid >> 5, lane = tid & 31;
    float* satt = sattb + w*128;

    for (int i = w; i < Cn; i += 8) {
        float sc[4];
        #pragma unroll
        for (int c = 0; c < 4; c++) {
            int kk = lane + 32*c;
            if (kk < Cn) {
                float s = 0.f;
                #pragma unroll
                for (int d = 0; d < 16; d++) s += sq[i*17 + d]*sk[kk*17 + d];
                sc[c] = s*0.25f;
            } else sc[c] = -1e30f;
        }
        float mx = fmaxf(fmaxf(sc[0], sc[1]), fmaxf(sc[2], sc[3]));
        #pragma unroll
        for (int o = 16; o > 0; o >>= 1) mx = fmaxf(mx, __shfl_xor_sync(0xffffffffu, mx, o));
        float p[4]; float sum = 0.f;
        #pragma unroll
        for (int c = 0; c < 4; c++) {
            int kk = lane + 32*c;
            p[c] = (kk < Cn) ? __expf(sc[c]-mx) : 0.f;
            sum += p[c];
        }
        #pragma unroll
        for (int o = 16; o > 0; o >>= 1) sum += __shfl_xor_sync(0xffffffffu, sum, o);
        float inv = __fdividef(1.f, sum);
        #pragma unroll
        for (int c = 0; c < 4; c++) {
            int kk = lane + 32*c;
            if (kk < Cn) satt[kk] = p[c]*inv;
        }
        __syncwarp();
        int d = lane & 15, half = lane >> 4;
        float a = 0.f;
        int j0 = half*61;
        for (int j = j0; j < j0 + 61; j++) a += satt[j]*sv[j*17 + d];
        a += __shfl_xor_sync(0xffffffffu, a, 16);
        if (lane < 16) ctx[(b*Cn + i)*Dn + h*16 + d] = a;
        __syncwarp();
    }
}

/* ============================================================
   Kernel 5: mean over C + per-subject head -> out[64,4]
   ============================================================ */
__global__ __launch_bounds__(128) void head_kernel(
    const float* __restrict__ tok, const int* __restrict__ sid,
    const float* __restrict__ hw, const float* __restrict__ hb,
    float* __restrict__ out)
{
    const int b = blockIdx.x;
    __shared__ float sp[128];
    const int d = threadIdx.x;
    float s = 0.f;
    for (int c = 0; c < Cn; c++) s += tok[(b*Cn + c)*Dn + d];
    sp[d] = s*(1.f/(float)Cn);
    __syncthreads();
    const int cls = threadIdx.x >> 5, lane = threadIdx.x & 31;
    const int sb = sid[b];
    float a = 0.f;
    #pragma unroll
    for (int i = 0; i < 4; i++) {
        int dd = lane + 32*i;
        a += sp[dd]*hw[(sb*4 + cls)*Dn + dd];
    }
    #pragma unroll
    for (int o = 16; o > 0; o >>= 1) a += __shfl_xor_sync(0xffffffffu, a, o);
    if (lane == 0) out[b*4 + cls] = a + hb[sb*4 + cls];
}

/* ============================================================ */
extern "C" void kernel_launch(void* const* d_in, const int* in_sizes, int n_in,
                              void* d_out, int out_size)
{
    const float* x       = (const float*)d_in[0];
    const int*   sid     = (const int*  )d_in[1];
    const float* conv1_w = (const float*)d_in[2];
    const float* conv1_b = (const float*)d_in[3];
    const float* bn1_g   = (const float*)d_in[4];
    const float* bn1_b   = (const float*)d_in[5];
    const float* bn1_m   = (const float*)d_in[6];
    const float* bn1_v   = (const float*)d_in[7];
    const float* conv2_w = (const float*)d_in[8];
    const float* conv2_b = (const float*)d_in[9];
    const float* bn2_g   = (const float*)d_in[10];
    const float* bn2_b   = (const float*)d_in[11];
    const float* bn2_m   = (const float*)d_in[12];
    const float* bn2_v   = (const float*)d_in[13];
    const float* proj_w  = (const float*)d_in[14];
    const float* proj_b  = (const float*)d_in[15];
    const float* emb     = (const float*)d_in[16];
    const float* qkv_w   = (const float*)d_in[17];
    const float* qkv_b   = (const float*)d_in[18];
    const float* out_w   = (const float*)d_in[19];
    const float* out_b   = (const float*)d_in[20];
    const float* ln1_g   = (const float*)d_in[21];
    const float* ln1_b   = (const float*)d_in[22];
    const float* ff1_w   = (const float*)d_in[23];
    const float* ff1_b   = (const float*)d_in[24];
    const float* ff2_w   = (const float*)d_in[25];
    const float* ff2_b   = (const float*)d_in[26];
    const float* ln2_g   = (const float*)d_in[27];
    const float* ln2_b   = (const float*)d_in[28];
    const float* heads_w = (const float*)d_in[29];
    const float* heads_b = (const float*)d_in[30];

    const int GEMM_SMEM   = (128*40 + 128*65)*4;           /* 53760 B  */
    const int GLN_SMEM128 = (128*40 + 128*65 + 32*132)*4;  /* 70656 B  */
    const int GLN_SMEM256 = (256*40 + 256*65 + 32*132)*4;  /* 124416 B */
    const int ATTN_SMEM   = (3*122*17 + 8*128)*4;          /* 28984 B  */

    cudaFuncSetAttribute(conv_kernel,    cudaFuncAttributeMaxDynamicSharedMemorySize, CONV_SMEM);
    cudaFuncSetAttribute(gemm_kernel,    cudaFuncAttributeMaxDynamicSharedMemorySize, GEMM_SMEM);
    cudaFuncSetAttribute(gemm_ln_kernel, cudaFuncAttributeMaxDynamicSharedMemorySize, GLN_SMEM256);
    cudaFuncSetAttribute(attn_kernel,    cudaFuncAttributeMaxDynamicSharedMemorySize, ATTN_SMEM);

    float* tokp = nullptr; float* qkvp = nullptr; float* ctxp = nullptr; float* ffp = nullptr;
    cudaGetSymbolAddress((void**)&tokp, g_tok);
    cudaGetSymbolAddress((void**)&qkvp, g_qkv);
    cudaGetSymbolAddress((void**)&ctxp, g_ctx);
    cudaGetSymbolAddress((void**)&ffp,  g_ff);

    uprep_kernel<<<8, 256>>>(conv2_w);

    conv_kernel<<<BC, 512, CONV_SMEM>>>(
        x, conv1_w, conv1_b, bn1_g, bn1_b, bn1_m, bn1_v,
        conv2_b, bn2_g, bn2_b, bn2_m, bn2_v,
        proj_w, proj_b, emb, tokp);

    for (int l = 0; l < Lln; l++) {
        gemm_kernel<<<dim3(244, 6), 256, GEMM_SMEM>>>(
            tokp, qkv_w + l*3*Dn*Dn, qkv_b + l*3*Dn, qkvp, Dn, 3*Dn, 0);
        attn_kernel<<<Bn*Hn, 256, ATTN_SMEM>>>(qkvp, ctxp);
        gemm_ln_kernel<<<244, 256, GLN_SMEM128>>>(
            ctxp, out_w + l*Dn*Dn, out_b + l*Dn,
            tokp, ln1_g + l*Dn, ln1_b + l*Dn, tokp, Dn);
        gemm_kernel<<<dim3(244, 4), 256, GEMM_SMEM>>>(
            tokp, ff1_w + l*FFn*Dn, ff1_b + l*FFn, ffp, Dn, FFn, 1);
        gemm_ln_kernel<<<244, 256, GLN_SMEM256>>>(
            ffp, ff2_w + l*Dn*FFn, ff2_b + l*Dn,
            tokp, ln2_g + l*Dn, ln2_b + l*Dn, tokp, FFn);
    }

    head_kernel<<<Bn, 128>>>(tokp, sid, heads_w, heads_b, (float*)d_out);
}

// round 16
// speedup vs baseline: 1.2440x; 1.1418x over previous
#include <cuda_runtime.h>
#include <cuda_fp16.h>

#define Bn   64
#define Cn   122
#define Tn   500
#define COn  64
#define Dn   128
#define Hn   8
#define FFn  256
#define Lln  2
#define BC   (Bn*Cn)        /* 7808 = 3904*2 */
#define EPSf 1e-5f

typedef unsigned long long ull;
typedef unsigned int uint32;

/* ---------------- scratch (device globals; no allocation) ---------------- */
__device__ float g_tok[BC*Dn];
__device__ float g_qkv[BC*3*Dn];
__device__ float g_ctx[BC*Dn];
__device__ float g_ff [BC*FFn];

/* fast erf-GELU: Abramowitz-Stegun 7.1.26, |erf err| <= 1.5e-7 */
__device__ __forceinline__ float gelu_f(float x){
    float z  = fabsf(x) * 0.70710678118654752440f;
    float t  = __fdividef(1.0f, 1.0f + 0.3275911f*z);
    float poly = t*(0.254829592f + t*(-0.284496736f +
                 t*(1.421413741f + t*(-1.453152027f + t*1.061405429f))));
    float erfz = 1.0f - poly*__expf(-z*z);
    float s = copysignf(erfz, x);
    return 0.5f*x*(1.0f + s);
}

/* packed f32x2 helpers (transformer GEMMs) */
__device__ __forceinline__ ull pk(float a, float b){
    ull r; asm("mov.b64 %0, {%1, %2};" : "=l"(r) : "f"(a), "f"(b)); return r;
}
__device__ __forceinline__ void fma2(ull& d, ull a, ull b){
    asm("fma.rn.f32x2 %0, %1, %2, %0;" : "+l"(d) : "l"(a), "l"(b));
}
__device__ __forceinline__ float2 upk(ull a){
    float2 f; asm("mov.b64 {%0, %1}, %2;" : "=f"(f.x), "=f"(f.y) : "l"(a)); return f;
}

/* fp16 mma m16n8k16, fp32 accum */
__device__ __forceinline__ void mma_f16(float* c,
    uint32 a0, uint32 a1, uint32 a2, uint32 a3, uint32 b0, uint32 b1){
    asm volatile("mma.sync.aligned.m16n8k16.row.col.f32.f16.f16.f32 "
        "{%0,%1,%2,%3}, {%4,%5,%6,%7}, {%8,%9}, {%0,%1,%2,%3};"
        : "+f"(c[0]), "+f"(c[1]), "+f"(c[2]), "+f"(c[3])
        : "r"(a0), "r"(a1), "r"(a2), "r"(a3), "r"(b0), "r"(b1));
}

__device__ __forceinline__ uint32 h2pack(__half lo, __half hi){
    __half2 h = __halves2half2(lo, hi);
    return *(uint32*)&h;
}

/* conv1 + BN + GELU + maxpool(2) -> actH/actL (fp16 split) */
__device__ __forceinline__ void conv1_run(
    int i0, int stride, const float* __restrict__ sx,
    const float* __restrict__ sw1,
    const float* __restrict__ sA1, const float* __restrict__ sB1,
    uint32* __restrict__ actH, uint32* __restrict__ actL)
{
    for (int i = i0; i < COn*250; i += stride) {
        int co = i / 250; int tp = i - co*250;
        const float* wp = &sw1[co*9];
        const float* xp = &sx[2*tp];
        float a0 = 0.f, a1 = 0.f;
        #pragma unroll
        for (int k = 0; k < 9; k++) { a0 += xp[k]*wp[k]; a1 += xp[k+1]*wp[k]; }
        float A = sA1[co], Bv = sB1[co];
        float y0 = gelu_f(a0*A + Bv);
        float y1 = gelu_f(a1*A + Bv);
        float m  = fmaxf(y0, y1);
        __half mh = __float2half_rn(m);
        __half ml = __float2half_rn(m - __half2float(mh));
        int hidx = ((co >> 1)*264 + 2 + tp)*2 + (co & 1);
        ((__half*)actH)[hidx] = mh;
        ((__half*)actL)[hidx] = ml;
    }
}

/* conv2 mma (3-term fp16) + BN/GELU/mean epilogue + proj, run by warps 0-7
   (256 threads). Internal sync via named barrier 1 (256 threads). */
__device__ __forceinline__ void mma_sample(
    const uint32* __restrict__ actH, const uint32* __restrict__ actL,
    const uint32* __restrict__ wH,   const uint32* __restrict__ wL,
    const float* __restrict__ sA2,   const float* __restrict__ sB2,
    float* __restrict__ spart, float* __restrict__ sh2,
    const float* __restrict__ pw, const float* __restrict__ pb,
    const float* __restrict__ emb, float* __restrict__ tok,
    int bc, int tid)
{
    const int wid = tid >> 5, lane = tid & 31;
    const int mchunk = wid & 1, tchunk = wid >> 1;   /* wid 0..7 */
    const int g = lane >> 2, t4 = lane & 3;

    float acc[2][8][4];
    #pragma unroll
    for (int mi = 0; mi < 2; mi++)
        #pragma unroll
        for (int nj = 0; nj < 8; nj++)
            #pragma unroll
            for (int r = 0; r < 4; r++) acc[mi][nj][r] = 0.f;

    const int mrow0 = mchunk*32 + g;
    const int nbase = tchunk*64 + g;

    #pragma unroll 4
    for (int c16 = 0; c16 < 20; c16++) {
        const int kk = c16 >> 2;
        const int rb = ((c16 & 3)*8 + t4)*264;
        const int q0 = c16*8 + t4;
        uint32 aH[2][4], aL[2][4];
        #pragma unroll
        for (int mi = 0; mi < 2; mi++) {
            int r0 = (mrow0 + mi*16)*164 + q0;
            int r1 = r0 + 8*164;
            aH[mi][0] = wH[r0];     aH[mi][1] = wH[r1];
            aH[mi][2] = wH[r0 + 4]; aH[mi][3] = wH[r1 + 4];
            aL[mi][0] = wL[r0];     aL[mi][1] = wL[r1];
            aL[mi][2] = wL[r0 + 4]; aL[mi][3] = wL[r1 + 4];
        }
        #pragma unroll
        for (int nj = 0; nj < 8; nj++) {
            int cb = rb + nbase + nj*8 + kk;
            uint32 bh0 = actH[cb], bh1 = actH[cb + 4*264];
            uint32 bl0 = actL[cb], bl1 = actL[cb + 4*264];
            #pragma unroll
            for (int mi = 0; mi < 2; mi++) {
                mma_f16(acc[mi][nj], aH[mi][0], aH[mi][1], aH[mi][2], aH[mi][3], bh0, bh1);
                mma_f16(acc[mi][nj], aH[mi][0], aH[mi][1], aH[mi][2], aH[mi][3], bl0, bl1);
                mma_f16(acc[mi][nj], aL[mi][0], aL[mi][1], aL[mi][2], aL[mi][3], bh0, bh1);
            }
        }
    }

    /* epilogue: BN + GELU + partial mean over t */
    #pragma unroll
    for (int mi = 0; mi < 2; mi++) {
        #pragma unroll
        for (int h = 0; h < 2; h++) {
            int r = mchunk*32 + mi*16 + g + h*8;
            float A = sA2[r], Bv = sB2[r];
            float rs = 0.f;
            #pragma unroll
            for (int nj = 0; nj < 8; nj++) {
                #pragma unroll
                for (int p = 0; p < 2; p++) {
                    int col = tchunk*64 + nj*8 + 2*t4 + p;
                    if (col < 250)
                        rs += gelu_f(acc[mi][nj][h*2+p]*A + Bv);
                }
            }
            rs += __shfl_xor_sync(0xffffffffu, rs, 1);
            rs += __shfl_xor_sync(0xffffffffu, rs, 2);
            if (t4 == 0) atomicAdd(&spart[r], rs);
        }
    }
    asm volatile("bar.sync 1, 256;" ::: "memory");
    if (tid < 64) sh2[tid] = spart[tid] * (1.f/250.f);
    asm volatile("bar.sync 1, 256;" ::: "memory");

    /* proj + elec_emb -> tok */
    if (tid < 128) {
        const int d = tid;
        float acc2 = pb[d];
        const float* pwr = &pw[d*COn];
        #pragma unroll 8
        for (int c = 0; c < 64; c++) acc2 += sh2[c]*__ldg(&pwr[c]);
        int cidx = bc % Cn;
        tok[bc*Dn + d] = acc2 + emb[cidx*Dn + d];
    }
}

/* ============================================================
   Kernel 1: fused conv pipeline (verified R9 best), 512 threads,
   2 samples/block, warp-specialized:
     stage A: all warps  : loads + conv1(s0)
     stage B: warps 0-7  : mma(s0)+epi+proj | warps 8-15: conv1(s1)
     stage C: warps 0-7  : mma(s1)+epi+proj
   SMEM (bytes), total 227584.
   ============================================================ */
__global__ void __launch_bounds__(512, 1) conv_kernel(
    const float* __restrict__ x,
    const float* __restrict__ w1, const float* __restrict__ cb1,
    const float* __restrict__ g1, const float* __restrict__ be1,
    const float* __restrict__ m1, const float* __restrict__ v1,
    const float* __restrict__ w2, const float* __restrict__ cb2,
    const float* __restrict__ g2, const float* __restrict__ be2,
    const float* __restrict__ m2, const float* __restrict__ v2,
    const float* __restrict__ pw, const float* __restrict__ pb,
    const float* __restrict__ emb, float* __restrict__ tok)
{
    extern __shared__ char smraw[];
    uint32* act0H = (uint32*)(smraw);
    uint32* act0L = (uint32*)(smraw + 33792);
    uint32* act1H = (uint32*)(smraw + 67584);
    uint32* act1L = (uint32*)(smraw + 101376);
    uint32* wH    = (uint32*)(smraw + 135168);
    uint32* wL    = (uint32*)(smraw + 177152);
    float* sx0    = (float*)(smraw + 219136);
    float* sx1    = (float*)(smraw + 221184);
    float* sw1    = (float*)(smraw + 223232);
    float* sA1    = (float*)(smraw + 225536);
    float* sB1    = sA1 + 64;
    float* sA2    = sA1 + 128;
    float* sB2    = sA1 + 192;
    float* spart0 = (float*)(smraw + 226560);
    float* spart1 = (float*)(smraw + 226816);
    float* sh20   = (float*)(smraw + 227072);
    float* sh21   = (float*)(smraw + 227328);

    const int bc0 = blockIdx.x*2;
    const int bc1 = bc0 + 1;
    const int tid = threadIdx.x;
    const int wid = tid >> 5;

    /* ---- stage A: all loads + conv1(s0) by all warps ---- */
    {
        int t = tid - 4;
        sx0[tid] = (t >= 0 && t < Tn) ? x[bc0*Tn + t] : 0.f;
        sx1[tid] = (t >= 0 && t < Tn) ? x[bc1*Tn + t] : 0.f;
    }
    for (int i = tid; i < COn*9; i += 512) sw1[i] = w1[i];
    if (tid < 64) {
        float a1 = g1[tid]*rsqrtf(v1[tid]+EPSf);
        sA1[tid] = a1;  sB1[tid] = (cb1[tid]-m1[tid])*a1 + be1[tid];
        float a2 = g2[tid]*rsqrtf(v2[tid]+EPSf);
        sA2[tid] = a2;  sB2[tid] = (cb2[tid]-m2[tid])*a2 + be2[tid];
        spart0[tid] = 0.f;  spart1[tid] = 0.f;
    }
    /* weights hi+lo: pair (k=2q, k=2q+1) = (ci, ci+1), same kk */
    for (int i = tid; i < COn*160; i += 512) {
        int co = i / 160, q = i - co*160;
        int k0 = 2*q;
        int kk = k0 >> 6, ci = k0 & 63;
        float wa = w2[co*320 + ci*5 + kk];
        float wb = w2[co*320 + (ci+1)*5 + kk];
        __half wah = __float2half_rn(wa);
        __half wbh = __float2half_rn(wb);
        wH[co*164 + q] = h2pack(wah, wbh);
        wL[co*164 + q] = h2pack(__float2half_rn(wa - __half2float(wah)),
                                __float2half_rn(wb - __half2float(wbh)));
    }
    /* zero pad cols {0,1} U [252,264) in all act arrays */
    for (int i = tid; i < 32*14; i += 512) {
        int row = i / 14, j = i - row*14;
        int col = (j < 2) ? j : (250 + j);
        act0H[row*264 + col] = 0u;  act0L[row*264 + col] = 0u;
        act1H[row*264 + col] = 0u;  act1L[row*264 + col] = 0u;
    }
    __syncthreads();

    conv1_run(tid, 512, sx0, sw1, sA1, sB1, act0H, act0L);
    __syncthreads();

    /* ---- stage B: mma(s0) || conv1(s1) ---- */
    if (wid < 8) {
        mma_sample(act0H, act0L, wH, wL, sA2, sB2, spart0, sh20,
                   pw, pb, emb, tok, bc0, tid);
    } else {
        conv1_run(tid - 256, 256, sx1, sw1, sA1, sB1, act1H, act1L);
    }
    __syncthreads();

    /* ---- stage C: mma(s1) ---- */
    if (wid < 8) {
        mma_sample(act1H, act1L, wH, wL, sA2, sB2, spart1, sh21,
                   pw, pb, emb, tok, bc1, tid);
    }
}

/* ============================================================
   Kernel 2: tiled GEMM  Y[M,N] = act(X[M,K] @ W[N,K]^T + bias)
   ============================================================ */
__global__ __launch_bounds__(256) void gemm_kernel(
    const float* __restrict__ X, const float* __restrict__ W,
    const float* __restrict__ bias, float* __restrict__ Y,
    int K, int N, int actGelu)
{
    extern __shared__ float sm[];
    float* sxT = sm;            /* [K][40] */
    float* swt = sm + K*40;     /* [K][65] */
    const int row0 = blockIdx.x*32;
    const int e0   = blockIdx.y*64;
    const int tid  = threadIdx.x;

    for (int li = tid; li < 32*K; li += 256) {
        int r = li / K, d = li - r*K;
        sxT[d*40 + r] = X[(row0+r)*K + d];
    }
    for (int li = tid; li < 64*K; li += 256) {
        int e = li / K, d = li - e*K;
        swt[d*65 + e] = W[(e0+e)*K + d];
    }
    __syncthreads();

    const int e_local = tid & 63, tg = tid >> 6;
    float bb = bias[e0 + e_local];
    ull acc[4];
    #pragma unroll
    for (int j = 0; j < 4; j++) acc[j] = pk(bb, bb);
    #pragma unroll 4
    for (int d = 0; d < K; d++) {
        ull Wp = pk(swt[d*65 + e_local], swt[d*65 + e_local]);
        const ull* tp = (const ull*)&sxT[d*40 + tg*8];
        fma2(acc[0], Wp, tp[0]);
        fma2(acc[1], Wp, tp[1]);
        fma2(acc[2], Wp, tp[2]);
        fma2(acc[3], Wp, tp[3]);
    }
    #pragma unroll
    for (int j = 0; j < 4; j++) {
        float2 y = upk(acc[j]);
        if (actGelu) { y.x = gelu_f(y.x); y.y = gelu_f(y.y); }
        Y[(row0 + tg*8 + 2*j  )*N + e0 + e_local] = y.x;
        Y[(row0 + tg*8 + 2*j+1)*N + e0 + e_local] = y.y;
    }
}

/* ============================================================
   Kernel 3: GEMM (N=128) + residual + LayerNorm epilogue
   ============================================================ */
__global__ __launch_bounds__(256) void gemm_ln_kernel(
    const float* __restrict__ X, const float* __restrict__ W,
    const float* __restrict__ bias,
    const float* __restrict__ Res,
    const float* __restrict__ lng, const float* __restrict__ lnb,
    float* __restrict__ Out, int K)
{
    extern __shared__ float sm[];
    float* sxT = sm;               /* [K][40]  */
    float* swt = sm + K*40;        /* [K][65]  */
    float* sy  = swt + K*65;       /* [32][132] */
    const int row0 = blockIdx.x*32;
    const int tid  = threadIdx.x;

    for (int li = tid; li < 32*K; li += 256) {
        int r = li / K, d = li - r*K;
        sxT[d*40 + r] = X[(row0+r)*K + d];
    }
    const int e_local = tid & 63, tg = tid >> 6;

    for (int e0 = 0; e0 < 128; e0 += 64) {
        __syncthreads();
        for (int li = tid; li < 64*K; li += 256) {
            int e = li / K, d = li - e*K;
            swt[d*65 + e] = W[(e0+e)*K + d];
        }
        __syncthreads();
        float bb = bias[e0 + e_local];
        ull acc[4];
        #pragma unroll
        for (int j = 0; j < 4; j++) acc[j] = pk(bb, bb);
        #pragma unroll 4
        for (int d = 0; d < K; d++) {
            ull Wp = pk(swt[d*65 + e_local], swt[d*65 + e_local]);
            const ull* tp = (const ull*)&sxT[d*40 + tg*8];
            fma2(acc[0], Wp, tp[0]);
            fma2(acc[1], Wp, tp[1]);
            fma2(acc[2], Wp, tp[2]);
            fma2(acc[3], Wp, tp[3]);
        }
        #pragma unroll
        for (int j = 0; j < 4; j++) {
            float2 y = upk(acc[j]);
            sy[(tg*8 + 2*j  )*132 + e0 + e_local] = y.x;
            sy[(tg*8 + 2*j+1)*132 + e0 + e_local] = y.y;
        }
    }
    __syncthreads();

    const int w = tid >> 5, lane = tid & 31;
    for (int q = 0; q < 4; q++) {
        int r = w*4 + q;
        float z[4]; float s1 = 0.f, s2 = 0.f;
        #pragma unroll
        for (int i = 0; i < 4; i++) {
            int idx = lane + 32*i;
            float zz = sy[r*132 + idx] + Res[(row0+r)*128 + idx];
            z[i] = zz; s1 += zz; s2 += zz*zz;
        }
        #pragma unroll
        for (int o = 16; o > 0; o >>= 1) {
            s1 += __shfl_xor_sync(0xffffffffu, s1, o);
            s2 += __shfl_xor_sync(0xffffffffu, s2, o);
        }
        float mean = s1*(1.f/128.f);
        float var  = s2*(1.f/128.f) - mean*mean;
        float rs   = rsqrtf(var + EPSf);
        #pragma unroll
        for (int i = 0; i < 4; i++) {
            int idx = lane + 32*i;
            Out[(row0+r)*128 + idx] = (z[i]-mean)*rs*lng[idx] + lnb[idx];
        }
    }
}

/* ============================================================
   Kernel 4: attention per (b, head), 256 threads, float4 LDS.
   Rows padded to 20 floats (16B aligned).
   ============================================================ */
__global__ __launch_bounds__(256) void attn_kernel(
    const float* __restrict__ qkv, float* __restrict__ ctx)
{
    const int b = blockIdx.x >> 3, h = blockIdx.x & 7;
    extern __shared__ float sm[];
    float* sq = sm;                 /* [122][20] */
    float* sk = sm + 122*20;
    float* sv = sm + 2*122*20;
    float* sattb = sm + 3*122*20;   /* [8][128] */
    const int tid = threadIdx.x;

    for (int li = tid; li < 122*4; li += 256) {
        int s = li >> 2, dq = (li & 3)*4;
        int base = (b*Cn + s)*384 + h*16 + dq;
        *(float4*)&sq[s*20 + dq] = *(const float4*)&qkv[base];
        *(float4*)&sk[s*20 + dq] = *(const float4*)&qkv[base + 128];
        *(float4*)&sv[s*20 + dq] = *(const float4*)&qkv[base + 256];
    }
    __syncthreads();

    const int w = tid >> 5, lane = tid & 31;
    float* satt = sattb + w*128;

    for (int i = w; i < Cn; i += 8) {
        float4 q0 = *(const float4*)&sq[i*20];
        float4 q1 = *(const float4*)&sq[i*20 + 4];
        float4 q2 = *(const float4*)&sq[i*20 + 8];
        float4 q3 = *(const float4*)&sq[i*20 + 12];
        float sc[4];
        #pragma unroll
        for (int c = 0; c < 4; c++) {
            int kk = lane + 32*c;
            if (kk < Cn) {
                const float4 k0 = *(const float4*)&sk[kk*20];
                const float4 k1 = *(const float4*)&sk[kk*20 + 4];
                const float4 k2 = *(const float4*)&sk[kk*20 + 8];
                const float4 k3 = *(const float4*)&sk[kk*20 + 12];
                float s = q0.x*k0.x + q0.y*k0.y + q0.z*k0.z + q0.w*k0.w
                        + q1.x*k1.x + q1.y*k1.y + q1.z*k1.z + q1.w*k1.w
                        + q2.x*k2.x + q2.y*k2.y + q2.z*k2.z + q2.w*k2.w
                        + q3.x*k3.x + q3.y*k3.y + q3.z*k3.z + q3.w*k3.w;
                sc[c] = s*0.25f;
            } else sc[c] = -1e30f;
        }
        float mx = fmaxf(fmaxf(sc[0], sc[1]), fmaxf(sc[2], sc[3]));
        #pragma unroll
        for (int o = 16; o > 0; o >>= 1) mx = fmaxf(mx, __shfl_xor_sync(0xffffffffu, mx, o));
        float p[4]; float sum = 0.f;
        #pragma unroll
        for (int c = 0; c < 4; c++) {
            int kk = lane + 32*c;
            p[c] = (kk < Cn) ? __expf(sc[c]-mx) : 0.f;
            sum += p[c];
        }
        #pragma unroll
        for (int o = 16; o > 0; o >>= 1) sum += __shfl_xor_sync(0xffffffffu, sum, o);
        float inv = __fdividef(1.f, sum);
        #pragma unroll
        for (int c = 0; c < 4; c++) {
            int kk = lane + 32*c;
            if (kk < Cn) satt[kk] = p[c]*inv;
        }
        __syncwarp();
        int d = lane & 15, half = lane >> 4;
        float a = 0.f;
        int j0 = half*61;
        #pragma unroll 4
        for (int j = j0; j < j0 + 61; j++) a += satt[j]*sv[j*20 + d];
        a += __shfl_xor_sync(0xffffffffu, a, 16);
        if (lane < 16) ctx[(b*Cn + i)*Dn + h*16 + d] = a;
        __syncwarp();
    }
}

/* ============================================================
   Kernel 5: mean over C + per-subject head -> out[64,4]
   ============================================================ */
__global__ __launch_bounds__(128) void head_kernel(
    const float* __restrict__ tok, const int* __restrict__ sid,
    const float* __restrict__ hw, const float* __restrict__ hb,
    float* __restrict__ out)
{
    const int b = blockIdx.x;
    __shared__ float sp[128];
    const int d = threadIdx.x;
    float s = 0.f;
    for (int c = 0; c < Cn; c++) s += tok[(b*Cn + c)*Dn + d];
    sp[d] = s*(1.f/(float)Cn);
    __syncthreads();
    const int cls = threadIdx.x >> 5, lane = threadIdx.x & 31;
    const int sb = sid[b];
    float a = 0.f;
    #pragma unroll
    for (int i = 0; i < 4; i++) {
        int dd = lane + 32*i;
        a += sp[dd]*hw[(sb*4 + cls)*Dn + dd];
    }
    #pragma unroll
    for (int o = 16; o > 0; o >>= 1) a += __shfl_xor_sync(0xffffffffu, a, o);
    if (lane == 0) out[b*4 + cls] = a + hb[sb*4 + cls];
}

/* ============================================================ */
extern "C" void kernel_launch(void* const* d_in, const int* in_sizes, int n_in,
                              void* d_out, int out_size)
{
    const float* x       = (const float*)d_in[0];
    const int*   sid     = (const int*  )d_in[1];
    const float* conv1_w = (const float*)d_in[2];
    const float* conv1_b = (const float*)d_in[3];
    const float* bn1_g   = (const float*)d_in[4];
    const float* bn1_b   = (const float*)d_in[5];
    const float* bn1_m   = (const float*)d_in[6];
    const float* bn1_v   = (const float*)d_in[7];
    const float* conv2_w = (const float*)d_in[8];
    const float* conv2_b = (const float*)d_in[9];
    const float* bn2_g   = (const float*)d_in[10];
    const float* bn2_b   = (const float*)d_in[11];
    const float* bn2_m   = (const float*)d_in[12];
    const float* bn2_v   = (const float*)d_in[13];
    const float* proj_w  = (const float*)d_in[14];
    const float* proj_b  = (const float*)d_in[15];
    const float* emb     = (const float*)d_in[16];
    const float* qkv_w   = (const float*)d_in[17];
    const float* qkv_b   = (const float*)d_in[18];
    const float* out_w   = (const float*)d_in[19];
    const float* out_b   = (const float*)d_in[20];
    const float* ln1_g   = (const float*)d_in[21];
    const float* ln1_b   = (const float*)d_in[22];
    const float* ff1_w   = (const float*)d_in[23];
    const float* ff1_b   = (const float*)d_in[24];
    const float* ff2_w   = (const float*)d_in[25];
    const float* ff2_b   = (const float*)d_in[26];
    const float* ln2_g   = (const float*)d_in[27];
    const float* ln2_b   = (const float*)d_in[28];
    const float* heads_w = (const float*)d_in[29];
    const float* heads_b = (const float*)d_in[30];

    const int CONV_SMEM   = 227584;                        /* bytes */
    const int GEMM_SMEM   = (128*40 + 128*65)*4;           /* 53760 B  */
    const int GLN_SMEM128 = (128*40 + 128*65 + 32*132)*4;  /* 70656 B  */
    const int GLN_SMEM256 = (256*40 + 256*65 + 32*132)*4;  /* 124416 B */
    const int ATTN_SMEM   = (3*122*20 + 8*128)*4;          /* 33376 B  */

    cudaFuncSetAttribute(conv_kernel,    cudaFuncAttributeMaxDynamicSharedMemorySize, CONV_SMEM);
    cudaFuncSetAttribute(gemm_kernel,    cudaFuncAttributeMaxDynamicSharedMemorySize, GEMM_SMEM);
    cudaFuncSetAttribute(gemm_ln_kernel, cudaFuncAttributeMaxDynamicSharedMemorySize, GLN_SMEM256);
    cudaFuncSetAttribute(attn_kernel,    cudaFuncAttributeMaxDynamicSharedMemorySize, ATTN_SMEM);

    float* tokp = nullptr; float* qkvp = nullptr; float* ctxp = nullptr; float* ffp = nullptr;
    cudaGetSymbolAddress((void**)&tokp, g_tok);
    cudaGetSymbolAddress((void**)&qkvp, g_qkv);
    cudaGetSymbolAddress((void**)&ctxp, g_ctx);
    cudaGetSymbolAddress((void**)&ffp,  g_ff);

    conv_kernel<<<BC/2, 512, CONV_SMEM>>>(
        x, conv1_w, conv1_b, bn1_g, bn1_b, bn1_m, bn1_v,
        conv2_w, conv2_b, bn2_g, bn2_b, bn2_m, bn2_v,
        proj_w, proj_b, emb, tokp);

    for (int l = 0; l < Lln; l++) {
        gemm_kernel<<<dim3(244, 6), 256, GEMM_SMEM>>>(
            tokp, qkv_w + l*3*Dn*Dn, qkv_b + l*3*Dn, qkvp, Dn, 3*Dn, 0);
        attn_kernel<<<Bn*Hn, 256, ATTN_SMEM>>>(qkvp, ctxp);
        gemm_ln_kernel<<<244, 256, GLN_SMEM128>>>(
            ctxp, out_w + l*Dn*Dn, out_b + l*Dn,
            tokp, ln1_g + l*Dn, ln1_b + l*Dn, tokp, Dn);
        gemm_kernel<<<dim3(244, 4), 256, GEMM_SMEM>>>(
            tokp, ff1_w + l*FFn*Dn, ff1_b + l*FFn, ffp, Dn, FFn, 1);
        gemm_ln_kernel<<<244, 256, GLN_SMEM256>>>(
            ffp, ff2_w + l*Dn*FFn, ff2_b + l*Dn,
            tokp, ln2_g + l*Dn, ln2_b + l*Dn, tokp, FFn);
    }

    head_kernel<<<Bn, 128>>>(tokp, sid, heads_w, heads_b, (float*)d_out);
}